// round 6
// baseline (speedup 1.0000x reference)
#include <cuda_runtime.h>

// ---------------- problem constants ----------------
#define B_      16
#define C_      256
#define HEADS_  8
#define D_      32          // dim_head
#define HW_     4096        // 64*64
#define W_      64
#define LN_EPS  1e-5f

// ---------------- scratch (no allocations allowed) ----------------
__device__ float    g_ctxp[(size_t)B_ * HEADS_ * 32 * (D_ * D_)]; // ctx partials
__device__ unsigned g_weff[(size_t)B_ * C_ * C_];                 // w_eff tf32 bits

// ---------------- helpers ----------------
__device__ __forceinline__ unsigned f2tf32(float f) {
    unsigned u;
    asm("cvt.rna.tf32.f32 %0, %1;" : "=r"(u) : "f"(f));
    return u;
}

__device__ __forceinline__ void mma_tf32(float* c, const unsigned* a, const unsigned* b) {
    asm volatile(
        "mma.sync.aligned.m16n8k8.row.col.f32.tf32.tf32.f32 "
        "{%0,%1,%2,%3}, {%4,%5,%6,%7}, {%8,%9}, {%0,%1,%2,%3};"
        : "+f"(c[0]), "+f"(c[1]), "+f"(c[2]), "+f"(c[3])
        : "r"(a[0]), "r"(a[1]), "r"(a[2]), "r"(a[3]), "r"(b[0]), "r"(b[1]));
}

__device__ __forceinline__ void cp16(void* sdst, const void* gsrc) {
    unsigned d = (unsigned)__cvta_generic_to_shared(sdst);
    asm volatile("cp.async.cg.shared.global [%0], [%1], 16;" :: "r"(d), "l"(gsrc));
}
#define CP_COMMIT()  asm volatile("cp.async.commit_group;")
#define CP_WAIT(n)   asm volatile("cp.async.wait_group %0;" :: "n"(n))

// ---------------- dynamic smem layouts ----------------
struct GemmBufs {
    float As[2][128][36];    // [m][k], pad 36
    float Bs[2][32][136];    // [k][n], pad 136
};
struct KvSmem {
    union {
        GemmBufs gb;
        float sc[128][132];  // [pixel][row] transposed tile for ctx compute
    } u;
    float red[2][4][64];     // k-softmax cross-warp partials
};
struct FusedSmem {
    float As[2][256][36];            // phase1: w_q fp32 chunks; phase2: w_eff tf32 bits
    union {
        float    Bs[2][32][136];     // phase1: x chunks
        unsigned qsm[256][136];      // phase1 output / phase2 B operand (tf32 bits)
    } u;
    float s_sum[128], s_sq[128], s_mu[128], s_rs[128];
};

// =====================================================================
// Kernel 1: fused kv GEMM + k-softmax + per-head context partial.
// grid (4 head-pairs, 32 pixel-tiles, 16 batches); block 256 (8 warps 2x4).
// =====================================================================
__global__ void __launch_bounds__(256) k_kv_ctx(const float* __restrict__ x,
                                                const float* __restrict__ w) {
    extern __shared__ char smem_raw[];
    KvSmem& S = *reinterpret_cast<KvSmem*>(smem_raw);

    const int tid  = threadIdx.x;
    const int warp = tid >> 5, lane = tid & 31;
    const int g = lane >> 2, tg = lane & 3;
    const int wm = warp >> 2, wn = warp & 3;

    const int hp = blockIdx.x;
    const int pt = blockIdx.y;
    const int b  = blockIdx.z;
    const int p0 = pt * 128;

    const float* xb = x + (size_t)b * (C_ * HW_) + p0;

    float acc[4][4][4] = {};

    // prologue: chunk 0
    {
#pragma unroll
        for (int i = 0; i < 4; i++) {
            int f4 = tid + i * 256;
            int ra = f4 >> 3, ca = (f4 & 7) << 2;
            int gr = (ra < 64) ? (C_ + hp * 64 + ra) : (2 * C_ + hp * 64 + ra - 64);
            cp16(&S.u.gb.As[0][ra][ca], &w[(size_t)gr * C_ + ca]);
            int rb = f4 >> 5, cb = (f4 & 31) << 2;
            cp16(&S.u.gb.Bs[0][rb][cb], &xb[(size_t)rb * HW_ + cb]);
        }
        CP_COMMIT();
    }

    for (int it = 0; it < 8; it++) {
        CP_WAIT(0);
        __syncthreads();
        if (it < 7) {
            const int k0n = (it + 1) * 32;
#pragma unroll
            for (int i = 0; i < 4; i++) {
                int f4 = tid + i * 256;
                int ra = f4 >> 3, ca = (f4 & 7) << 2;
                int gr = (ra < 64) ? (C_ + hp * 64 + ra) : (2 * C_ + hp * 64 + ra - 64);
                cp16(&S.u.gb.As[(it + 1) & 1][ra][ca], &w[(size_t)gr * C_ + k0n + ca]);
                int rb = f4 >> 5, cb = (f4 & 31) << 2;
                cp16(&S.u.gb.Bs[(it + 1) & 1][rb][cb], &xb[(size_t)(k0n + rb) * HW_ + cb]);
            }
            CP_COMMIT();
        }
        const int bu = it & 1;
#pragma unroll
        for (int ks = 0; ks < 4; ks++) {
            const int kb = ks * 8;
            unsigned af[4][4], bf[4][2];
#pragma unroll
            for (int mt = 0; mt < 4; mt++) {
                int rm = wm * 64 + mt * 16;
                af[mt][0] = f2tf32(S.u.gb.As[bu][rm + g][kb + tg]);
                af[mt][1] = f2tf32(S.u.gb.As[bu][rm + g + 8][kb + tg]);
                af[mt][2] = f2tf32(S.u.gb.As[bu][rm + g][kb + tg + 4]);
                af[mt][3] = f2tf32(S.u.gb.As[bu][rm + g + 8][kb + tg + 4]);
            }
#pragma unroll
            for (int nt = 0; nt < 4; nt++) {
                int cn = wn * 32 + nt * 8 + g;
                bf[nt][0] = f2tf32(S.u.gb.Bs[bu][kb + tg][cn]);
                bf[nt][1] = f2tf32(S.u.gb.Bs[bu][kb + tg + 4][cn]);
            }
#pragma unroll
            for (int mt = 0; mt < 4; mt++)
#pragma unroll
                for (int nt = 0; nt < 4; nt++)
                    mma_tf32(acc[mt][nt], af[mt], bf[nt]);
        }
    }

    // ---- k-softmax over y=64 (rows 0-63 -> wm==0 warps)
    float mloc[4][2], sloc[4][2];
    if (wm == 0) {
#pragma unroll
        for (int mt = 0; mt < 4; mt++)
#pragma unroll
            for (int hf = 0; hf < 2; hf++) {
                float m = -1e30f;
#pragma unroll
                for (int nt = 0; nt < 4; nt++) {
                    m = fmaxf(m, acc[mt][nt][hf * 2]);
                    m = fmaxf(m, acc[mt][nt][hf * 2 + 1]);
                }
                m = fmaxf(m, __shfl_xor_sync(0xffffffffu, m, 1));
                m = fmaxf(m, __shfl_xor_sync(0xffffffffu, m, 2));
                mloc[mt][hf] = m;
                if (tg == 0) S.red[0][wn][mt * 16 + hf * 8 + g] = m;
            }
    }
    __syncthreads();
    if (wm == 0) {
#pragma unroll
        for (int mt = 0; mt < 4; mt++)
#pragma unroll
            for (int hf = 0; hf < 2; hf++) {
                int ri = mt * 16 + hf * 8 + g;
                float m = fmaxf(mloc[mt][hf], S.red[0][wn ^ 1][ri]);
                float s = 0.f;
#pragma unroll
                for (int nt = 0; nt < 4; nt++) {
                    float e0 = __expf(acc[mt][nt][hf * 2] - m);
                    float e1 = __expf(acc[mt][nt][hf * 2 + 1] - m);
                    acc[mt][nt][hf * 2]     = e0;
                    acc[mt][nt][hf * 2 + 1] = e1;
                    s += e0 + e1;
                }
                s += __shfl_xor_sync(0xffffffffu, s, 1);
                s += __shfl_xor_sync(0xffffffffu, s, 2);
                sloc[mt][hf] = s;
                if (tg == 0) S.red[1][wn][ri] = s;
            }
    }
    __syncthreads();
    if (wm == 0) {
#pragma unroll
        for (int mt = 0; mt < 4; mt++)
#pragma unroll
            for (int hf = 0; hf < 2; hf++) {
                int ri = mt * 16 + hf * 8 + g;
                float inv = 1.0f / (sloc[mt][hf] + S.red[1][wn ^ 1][ri]);
#pragma unroll
                for (int nt = 0; nt < 4; nt++) {
                    acc[mt][nt][hf * 2]     *= inv;
                    acc[mt][nt][hf * 2 + 1] *= inv;
                }
            }
    }
    __syncthreads();   // all mainloop smem reads done; safe to overlay sc

#pragma unroll
    for (int mt = 0; mt < 4; mt++) {
        int r0 = wm * 64 + mt * 16 + g;
#pragma unroll
        for (int nt = 0; nt < 4; nt++) {
            int c = wn * 32 + nt * 8 + tg * 2;
            S.u.sc[c][r0]         = acc[mt][nt][0];
            S.u.sc[c + 1][r0]     = acc[mt][nt][1];
            S.u.sc[c][r0 + 8]     = acc[mt][nt][2];
            S.u.sc[c + 1][r0 + 8] = acc[mt][nt][3];
        }
    }
    __syncthreads();

    // ctx partial per head: ctx[d][e] = sum_p khat[d][p] * v[e][p]
    {
        const int h  = tid >> 7;
        const int tl = tid & 127;
        const int td = tl >> 3;
        const int te = tl & 7;
        const int d0 = h * 32 + td * 2;
        const int e0 = 64 + h * 32 + te * 4;

        float a00 = 0.f, a01 = 0.f, a02 = 0.f, a03 = 0.f;
        float a10 = 0.f, a11 = 0.f, a12 = 0.f, a13 = 0.f;
#pragma unroll 8
        for (int p = 0; p < 128; p++) {
            float2 kk = *(const float2*)&S.u.sc[p][d0];
            float4 vv = *(const float4*)&S.u.sc[p][e0];
            a00 += kk.x * vv.x; a01 += kk.x * vv.y; a02 += kk.x * vv.z; a03 += kk.x * vv.w;
            a10 += kk.y * vv.x; a11 += kk.y * vv.y; a12 += kk.y * vv.z; a13 += kk.y * vv.w;
        }
        float* op = g_ctxp + (((size_t)(b * HEADS_ + hp * 2 + h)) * 32 + pt) * (D_ * D_);
        *(float4*)&op[(td * 2 + 0) * D_ + te * 4] = make_float4(a00, a01, a02, a03);
        *(float4*)&op[(td * 2 + 1) * D_ + te * 4] = make_float4(a10, a11, a12, a13);
    }
}

// =====================================================================
// Kernel 2: reduce ctx partials + w_eff = w_out(head slice) @ ctx (tf32 bits)
// =====================================================================
__global__ void __launch_bounds__(256) k_weff(const float* __restrict__ w_out) {
    const int h = blockIdx.x, b = blockIdx.y;
    const int bh = b * HEADS_ + h;
    const int t = threadIdx.x;

    __shared__ float ctxs[32][33];
    __shared__ float ws[256][33];

    const float* pp = g_ctxp + (size_t)bh * 32 * (D_ * D_);
#pragma unroll
    for (int i = 0; i < 4; i++) {
        int elem = t + i * 256;
        float s = 0.f;
#pragma unroll
        for (int pg = 0; pg < 32; pg++) s += pp[pg * (D_ * D_) + elem];
        ctxs[elem >> 5][elem & 31] = s;
    }
#pragma unroll
    for (int i = 0; i < 32; i++) {
        int idx = t + i * 256;
        int r = idx >> 5, c = idx & 31;
        ws[r][c] = w_out[(size_t)r * C_ + h * D_ + c];
    }
    __syncthreads();

    float we[32] = {};
#pragma unroll
    for (int d = 0; d < 32; d++) {
        float wv = ws[t][d];
#pragma unroll
        for (int e = 0; e < 32; e++) we[e] += wv * ctxs[d][e];
    }
    unsigned* op = g_weff + ((size_t)b * C_ + t) * C_ + h * D_;
#pragma unroll
    for (int e4 = 0; e4 < 8; e4++) {
        uint4 u = make_uint4(f2tf32(we[e4 * 4]), f2tf32(we[e4 * 4 + 1]),
                             f2tf32(we[e4 * 4 + 2]), f2tf32(we[e4 * 4 + 3]));
        *(uint4*)&op[e4 * 4] = u;
    }
}

// =====================================================================
// Kernel 3: FUSED  qhat = softmax_d(w_q @ x)  ->  out = w_eff @ qhat + LN.
// 512 threads (16 warps 4x4), 128-pixel tiles, qhat lives only in smem.
// =====================================================================
__global__ void __launch_bounds__(512) k_fused(const float* __restrict__ x,
                                               const float* __restrict__ w,
                                               const float* __restrict__ b_out,
                                               const float* __restrict__ gamma,
                                               const float* __restrict__ beta,
                                               float* __restrict__ out) {
    extern __shared__ char smem_raw[];
    FusedSmem& S = *reinterpret_cast<FusedSmem*>(smem_raw);

    const int tid  = threadIdx.x;
    const int warp = tid >> 5, lane = tid & 31;
    const int g = lane >> 2, tg = lane & 3;
    const int wm = warp >> 2, wn = warp & 3;     // 4 x 4 warp grid

    const int b  = blockIdx.x >> 5;
    const int p0 = (blockIdx.x & 31) * 128;

    const float*    xb = x + (size_t)b * (C_ * HW_) + p0;
    const unsigned* wb = g_weff + (size_t)b * C_ * C_;

    if (tid < 128) { S.s_sum[tid] = 0.f; S.s_sq[tid] = 0.f; }

    float acc[4][4][4] = {};

    // ============== PHASE 1: qhat = softmax_d(w_q @ x_tile) ==============
    {
#pragma unroll
        for (int i = 0; i < 4; i++) {
            int f4 = tid + i * 512;
            int ra = f4 >> 3, ca = (f4 & 7) << 2;
            cp16(&S.As[0][ra][ca], &w[(size_t)ra * C_ + ca]);
        }
#pragma unroll
        for (int i = 0; i < 2; i++) {
            int f4 = tid + i * 512;
            int rb = f4 >> 5, cb = (f4 & 31) << 2;
            cp16(&S.u.Bs[0][rb][cb], &xb[(size_t)rb * HW_ + cb]);
        }
        CP_COMMIT();
    }

    for (int it = 0; it < 8; it++) {
        CP_WAIT(0);
        __syncthreads();
        if (it < 7) {
            const int k0n = (it + 1) * 32;
#pragma unroll
            for (int i = 0; i < 4; i++) {
                int f4 = tid + i * 512;
                int ra = f4 >> 3, ca = (f4 & 7) << 2;
                cp16(&S.As[(it + 1) & 1][ra][ca], &w[(size_t)ra * C_ + k0n + ca]);
            }
#pragma unroll
            for (int i = 0; i < 2; i++) {
                int f4 = tid + i * 512;
                int rb = f4 >> 5, cb = (f4 & 31) << 2;
                cp16(&S.u.Bs[(it + 1) & 1][rb][cb], &xb[(size_t)(k0n + rb) * HW_ + cb]);
            }
            CP_COMMIT();
        }
        const int bu = it & 1;
#pragma unroll
        for (int ks = 0; ks < 4; ks++) {
            const int kb = ks * 8;
            unsigned af[4][4], bf[4][2];
#pragma unroll
            for (int mt = 0; mt < 4; mt++) {
                int rm = wm * 64 + mt * 16;
                af[mt][0] = f2tf32(S.As[bu][rm + g][kb + tg]);
                af[mt][1] = f2tf32(S.As[bu][rm + g + 8][kb + tg]);
                af[mt][2] = f2tf32(S.As[bu][rm + g][kb + tg + 4]);
                af[mt][3] = f2tf32(S.As[bu][rm + g + 8][kb + tg + 4]);
            }
#pragma unroll
            for (int nt = 0; nt < 4; nt++) {
                int cn = wn * 32 + nt * 8 + g;
                bf[nt][0] = f2tf32(S.u.Bs[bu][kb + tg][cn]);
                bf[nt][1] = f2tf32(S.u.Bs[bu][kb + tg + 4][cn]);
            }
#pragma unroll
            for (int mt = 0; mt < 4; mt++)
#pragma unroll
                for (int nt = 0; nt < 4; nt++)
                    mma_tf32(acc[mt][nt], af[mt], bf[nt]);
        }
    }

    // prefetch phase-2 chunk 0 (w_eff) into As[0] — overlaps softmax/interlude.
    // Safe: As[0] last read at it=6; all warps passed the it=7 barrier.
    {
#pragma unroll
        for (int i = 0; i < 4; i++) {
            int f4 = tid + i * 512;
            int ra = f4 >> 3, ca = (f4 & 7) << 2;
            cp16(&S.As[0][ra][ca], &wb[(size_t)ra * C_ + ca]);
        }
        CP_COMMIT();
    }

    // q-softmax over d=32 (head = mt-pair; rows span g via shfl)
#pragma unroll
    for (int p = 0; p < 2; p++) {
#pragma unroll
        for (int nt = 0; nt < 4; nt++) {
#pragma unroll
            for (int j = 0; j < 2; j++) {
                float v0 = acc[2 * p][nt][j],     v1 = acc[2 * p][nt][j + 2];
                float v2 = acc[2 * p + 1][nt][j], v3 = acc[2 * p + 1][nt][j + 2];
                float m = fmaxf(fmaxf(v0, v1), fmaxf(v2, v3));
                m = fmaxf(m, __shfl_xor_sync(0xffffffffu, m, 4));
                m = fmaxf(m, __shfl_xor_sync(0xffffffffu, m, 8));
                m = fmaxf(m, __shfl_xor_sync(0xffffffffu, m, 16));
                float e0 = __expf(v0 - m), e1 = __expf(v1 - m);
                float e2 = __expf(v2 - m), e3 = __expf(v3 - m);
                float s = e0 + e1 + e2 + e3;
                s += __shfl_xor_sync(0xffffffffu, s, 4);
                s += __shfl_xor_sync(0xffffffffu, s, 8);
                s += __shfl_xor_sync(0xffffffffu, s, 16);
                float inv = 1.0f / s;
                acc[2 * p][nt][j]         = e0 * inv;
                acc[2 * p][nt][j + 2]     = e1 * inv;
                acc[2 * p + 1][nt][j]     = e2 * inv;
                acc[2 * p + 1][nt][j + 2] = e3 * inv;
            }
        }
    }

    __syncthreads();   // all warps done reading Bs -> safe to overlay qsm
#pragma unroll
    for (int mt = 0; mt < 4; mt++) {
        int r0 = wm * 64 + mt * 16 + g;
#pragma unroll
        for (int nt = 0; nt < 4; nt++) {
            int c = wn * 32 + nt * 8 + tg * 2;
            S.u.qsm[r0][c]         = f2tf32(acc[mt][nt][0]);
            S.u.qsm[r0][c + 1]     = f2tf32(acc[mt][nt][1]);
            S.u.qsm[r0 + 8][c]     = f2tf32(acc[mt][nt][2]);
            S.u.qsm[r0 + 8][c + 1] = f2tf32(acc[mt][nt][3]);
        }
    }
    __syncthreads();

#pragma unroll
    for (int mt = 0; mt < 4; mt++)
#pragma unroll
        for (int nt = 0; nt < 4; nt++)
#pragma unroll
            for (int j = 0; j < 4; j++)
                acc[mt][nt][j] = 0.f;

    // ============== PHASE 2: out = w_eff @ qhat (B resident in smem) =====
    for (int it = 0; it < 8; it++) {
        CP_WAIT(0);
        __syncthreads();
        if (it < 7) {
            const int k0n = (it + 1) * 32;
#pragma unroll
            for (int i = 0; i < 4; i++) {
                int f4 = tid + i * 512;
                int ra = f4 >> 3, ca = (f4 & 7) << 2;
                cp16(&S.As[(it + 1) & 1][ra][ca], &wb[(size_t)ra * C_ + k0n + ca]);
            }
            CP_COMMIT();
        }
        const int bu = it & 1;
        const int k0 = it * 32;
#pragma unroll
        for (int ks = 0; ks < 4; ks++) {
            const int kb = ks * 8;
            unsigned af[4][4], bf[4][2];
#pragma unroll
            for (int mt = 0; mt < 4; mt++) {
                int rm = wm * 64 + mt * 16;
                af[mt][0] = __float_as_uint(S.As[bu][rm + g][kb + tg]);
                af[mt][1] = __float_as_uint(S.As[bu][rm + g + 8][kb + tg]);
                af[mt][2] = __float_as_uint(S.As[bu][rm + g][kb + tg + 4]);
                af[mt][3] = __float_as_uint(S.As[bu][rm + g + 8][kb + tg + 4]);
            }
#pragma unroll
            for (int nt = 0; nt < 4; nt++) {
                int cn = wn * 32 + nt * 8 + g;
                bf[nt][0] = S.u.qsm[k0 + kb + tg][cn];
                bf[nt][1] = S.u.qsm[k0 + kb + tg + 4][cn];
            }
#pragma unroll
            for (int mt = 0; mt < 4; mt++)
#pragma unroll
                for (int nt = 0; nt < 4; nt++)
                    mma_tf32(acc[mt][nt], af[mt], bf[nt]);
        }
    }

    // ============== epilogue: bias + channel LayerNorm + store ==========
    float bias0[4], bias1[4], gam0[4], gam1[4], bet0[4], bet1[4];
#pragma unroll
    for (int mt = 0; mt < 4; mt++) {
        int r = wm * 64 + mt * 16 + g;
        bias0[mt] = b_out[r]; bias1[mt] = b_out[r + 8];
        gam0[mt]  = gamma[r]; gam1[mt]  = gamma[r + 8];
        bet0[mt]  = beta[r];  bet1[mt]  = beta[r + 8];
    }
#pragma unroll
    for (int mt = 0; mt < 4; mt++)
#pragma unroll
        for (int nt = 0; nt < 4; nt++) {
            acc[mt][nt][0] += bias0[mt]; acc[mt][nt][1] += bias0[mt];
            acc[mt][nt][2] += bias1[mt]; acc[mt][nt][3] += bias1[mt];
        }

#pragma unroll
    for (int nt = 0; nt < 4; nt++) {
        float s0 = 0.f, s1 = 0.f, q0 = 0.f, q1 = 0.f;
#pragma unroll
        for (int mt = 0; mt < 4; mt++) {
            float v0 = acc[mt][nt][0], v1 = acc[mt][nt][1];
            float v2 = acc[mt][nt][2], v3 = acc[mt][nt][3];
            s0 += v0 + v2; s1 += v1 + v3;
            q0 += v0 * v0 + v2 * v2; q1 += v1 * v1 + v3 * v3;
        }
#pragma unroll
        for (int off = 4; off < 32; off <<= 1) {
            s0 += __shfl_xor_sync(0xffffffffu, s0, off);
            s1 += __shfl_xor_sync(0xffffffffu, s1, off);
            q0 += __shfl_xor_sync(0xffffffffu, q0, off);
            q1 += __shfl_xor_sync(0xffffffffu, q1, off);
        }
        if (g == 0) {
            int c = wn * 32 + nt * 8 + tg * 2;
            atomicAdd(&S.s_sum[c], s0);     atomicAdd(&S.s_sq[c], q0);
            atomicAdd(&S.s_sum[c + 1], s1); atomicAdd(&S.s_sq[c + 1], q1);
        }
    }
    __syncthreads();

    if (tid < 128) {
        float mu  = S.s_sum[tid] * (1.0f / 256.0f);
        float var = S.s_sq[tid] * (1.0f / 256.0f) - mu * mu;
        S.s_mu[tid] = mu;
        S.s_rs[tid] = rsqrtf(var + LN_EPS);
    }
    __syncthreads();

    float* ob = out + (size_t)b * (C_ * HW_) + p0;
#pragma unroll
    for (int mt = 0; mt < 4; mt++) {
        int r = wm * 64 + mt * 16 + g;
#pragma unroll
        for (int nt = 0; nt < 4; nt++) {
            int c = wn * 32 + nt * 8 + tg * 2;
            float mu0 = S.s_mu[c], rs0 = S.s_rs[c];
            float mu1 = S.s_mu[c + 1], rs1 = S.s_rs[c + 1];
            float o0 = (acc[mt][nt][0] - mu0) * rs0 * gam0[mt] + bet0[mt];
            float o1 = (acc[mt][nt][1] - mu1) * rs1 * gam0[mt] + bet0[mt];
            float o2 = (acc[mt][nt][2] - mu0) * rs0 * gam1[mt] + bet1[mt];
            float o3 = (acc[mt][nt][3] - mu1) * rs1 * gam1[mt] + bet1[mt];
            *(float2*)&ob[(size_t)r * HW_ + c]       = make_float2(o0, o1);
            *(float2*)&ob[(size_t)(r + 8) * HW_ + c] = make_float2(o2, o3);
        }
    }
}

// =====================================================================
extern "C" void kernel_launch(void* const* d_in, const int* in_sizes, int n_in,
                              void* d_out, int out_size) {
    const float* x      = (const float*)d_in[0];
    const float* w_qkv  = (const float*)d_in[1];
    const float* w_out  = (const float*)d_in[2];
    const float* b_out  = (const float*)d_in[3];
    const float* gamma  = (const float*)d_in[4];
    const float* beta   = (const float*)d_in[5];
    float* out = (float*)d_out;

    cudaFuncSetAttribute(k_kv_ctx, cudaFuncAttributeMaxDynamicSharedMemorySize,
                         (int)sizeof(KvSmem));
    cudaFuncSetAttribute(k_fused, cudaFuncAttributeMaxDynamicSharedMemorySize,
                         (int)sizeof(FusedSmem));

    dim3 g1(4, 32, B_);                           // head-pairs x pixel-tiles x batch
    k_kv_ctx<<<g1, 256, sizeof(KvSmem)>>>(x, w_qkv);

    dim3 g2(HEADS_, B_);                          // 8 x 16
    k_weff<<<g2, 256>>>(w_out);

    k_fused<<<(B_ * HW_) / 128, 512, sizeof(FusedSmem)>>>(x, w_qkv, b_out, gamma, beta, out);
}

// round 8
// speedup vs baseline: 1.0177x; 1.0177x over previous
#include <cuda_runtime.h>

// ---------------- problem constants ----------------
#define B_      16
#define C_      256
#define HEADS_  8
#define D_      32          // dim_head
#define HW_     4096        // 64*64
#define W_      64
#define LN_EPS  1e-5f

// ---------------- scratch (no allocations allowed) ----------------
__device__ unsigned g_x[(size_t)B_ * C_ * HW_];        // x as tf32 bit patterns
__device__ unsigned g_wq[3 * C_ * C_];                 // w_qkv as tf32 bit patterns
__device__ float    g_q[(size_t)B_ * C_ * HW_];        // qhat as tf32 bit patterns
__device__ float    g_ctxp[(size_t)B_ * HEADS_ * 32 * (D_ * D_)];
__device__ unsigned g_weff[(size_t)B_ * C_ * C_];      // w_eff tf32 bits

// ---------------- helpers ----------------
__device__ __forceinline__ unsigned f2tf32(float f) {
    unsigned u;
    asm("cvt.rna.tf32.f32 %0, %1;" : "=r"(u) : "f"(f));
    return u;
}

__device__ __forceinline__ void mma_tf32(float* c, const unsigned* a, const unsigned* b) {
    asm volatile(
        "mma.sync.aligned.m16n8k8.row.col.f32.tf32.tf32.f32 "
        "{%0,%1,%2,%3}, {%4,%5,%6,%7}, {%8,%9}, {%0,%1,%2,%3};"
        : "+f"(c[0]), "+f"(c[1]), "+f"(c[2]), "+f"(c[3])
        : "r"(a[0]), "r"(a[1]), "r"(a[2]), "r"(a[3]), "r"(b[0]), "r"(b[1]));
}

__device__ __forceinline__ unsigned s2u(const void* p) {
    return (unsigned)__cvta_generic_to_shared(p);
}
__device__ __forceinline__ void cp16s(unsigned sdst, const void* gsrc) {
    asm volatile("cp.async.cg.shared.global [%0], [%1], 16;" :: "r"(sdst), "l"(gsrc));
}
#define CP_COMMIT()  asm volatile("cp.async.commit_group;")
#define CP_WAIT(n)   asm volatile("cp.async.wait_group %0;" :: "n"(n))

// ---------------- dynamic smem layouts ----------------
struct GemmBufs {
    unsigned As[2][128][36];   // [m][k] tf32 bits, pad 36
    unsigned Bs[2][32][136];   // [k][n] tf32 bits, pad 136
};
struct KvSmem {
    union {
        GemmBufs gb;
        float sc[128][132];    // [pixel][row] transposed tile for ctx compute
    } u;
    float red[2][4][64];       // k-softmax cross-warp partials
};
struct OutSmem {
    unsigned As[2][256][36];
    unsigned Bs[2][32][72];
    float s_sum[64], s_sq[64], s_mu[64], s_rs[64];
};

// =====================================================================
// Kernel 0a/0b: pre-convert x and w_qkv to tf32 bit patterns (vectorized)
// =====================================================================
__global__ void __launch_bounds__(256) k_prex(const float* __restrict__ x) {
    size_t i = (size_t)blockIdx.x * 256 + threadIdx.x;
    float4 v = ((const float4*)x)[i];
    uint4 u = make_uint4(f2tf32(v.x), f2tf32(v.y), f2tf32(v.z), f2tf32(v.w));
    ((uint4*)g_x)[i] = u;
}
__global__ void __launch_bounds__(256) k_prew(const float* __restrict__ w) {
    size_t i = (size_t)blockIdx.x * 256 + threadIdx.x;
    float4 v = ((const float4*)w)[i];
    uint4 u = make_uint4(f2tf32(v.x), f2tf32(v.y), f2tf32(v.z), f2tf32(v.w));
    ((uint4*)g_wq)[i] = u;
}

// =====================================================================
// Kernel 1: qhat = softmax_d(w_q @ x)  — zero-CVT mainloop, hoisted addrs
// grid (512 pixel-tiles, 2 row-blocks); 256 threads (8 warps 2x4).
// =====================================================================
__global__ void __launch_bounds__(256) k_q_gemm() {
    extern __shared__ char smem_raw[];
    GemmBufs& S = *reinterpret_cast<GemmBufs*>(smem_raw);

    const int tid  = threadIdx.x;
    const int warp = tid >> 5, lane = tid & 31;
    const int g = lane >> 2, tg = lane & 3;
    const int wm = warp >> 2, wn = warp & 3;

    const int m0 = blockIdx.y * 128;
    const size_t n0 = (size_t)blockIdx.x * 128;
    const int b  = (int)(n0 >> 12);
    const int p0 = (int)(n0 & 4095);

    const unsigned* xb = g_x + (size_t)b * (C_ * HW_) + p0;
    float* ob = g_q + (size_t)b * (C_ * HW_) + p0;

    // hoisted per-thread load pointers + smem dst addresses
    const unsigned* pa[4]; const unsigned* pb[4];
    unsigned sa[2][4], sb[2][4];
#pragma unroll
    for (int i = 0; i < 4; i++) {
        int f4 = tid + i * 256;
        int ra = f4 >> 3, ca = (f4 & 7) << 2;
        pa[i] = g_wq + (size_t)(m0 + ra) * C_ + ca;
        sa[0][i] = s2u(&S.As[0][ra][ca]);
        sa[1][i] = s2u(&S.As[1][ra][ca]);
        int rb = f4 >> 5, cb = (f4 & 31) << 2;
        pb[i] = xb + (size_t)rb * HW_ + cb;
        sb[0][i] = s2u(&S.Bs[0][rb][cb]);
        sb[1][i] = s2u(&S.Bs[1][rb][cb]);
    }

    float acc[4][4][4] = {};

    // prologue: chunk 0
#pragma unroll
    for (int i = 0; i < 4; i++) {
        cp16s(sa[0][i], pa[i]);  pa[i] += 32;
        cp16s(sb[0][i], pb[i]);  pb[i] += 32 * HW_;
    }
    CP_COMMIT();

    int buf = 0;
    for (int it = 0; it < 8; it++) {
        if (it < 7) {
#pragma unroll
            for (int i = 0; i < 4; i++) {
                cp16s(sa[buf ^ 1][i], pa[i]);  pa[i] += 32;
                cp16s(sb[buf ^ 1][i], pb[i]);  pb[i] += 32 * HW_;
            }
            CP_COMMIT();
            CP_WAIT(1);
        } else {
            CP_WAIT(0);
        }
        __syncthreads();
#pragma unroll
        for (int ks = 0; ks < 4; ks++) {
            const int kb = ks * 8;
            unsigned af[4][4], bf[4][2];
#pragma unroll
            for (int mt = 0; mt < 4; mt++) {
                int rm = wm * 64 + mt * 16;
                af[mt][0] = S.As[buf][rm + g][kb + tg];
                af[mt][1] = S.As[buf][rm + g + 8][kb + tg];
                af[mt][2] = S.As[buf][rm + g][kb + tg + 4];
                af[mt][3] = S.As[buf][rm + g + 8][kb + tg + 4];
            }
#pragma unroll
            for (int nt = 0; nt < 4; nt++) {
                int cn = wn * 32 + nt * 8 + g;
                bf[nt][0] = S.Bs[buf][kb + tg][cn];
                bf[nt][1] = S.Bs[buf][kb + tg + 4][cn];
            }
#pragma unroll
            for (int mt = 0; mt < 4; mt++)
#pragma unroll
                for (int nt = 0; nt < 4; nt++)
                    mma_tf32(acc[mt][nt], af[mt], bf[nt]);
        }
        __syncthreads();
        buf ^= 1;
    }

    // q-softmax over d=32 (head = mt-pair; rows span g via shfl)
#pragma unroll
    for (int p = 0; p < 2; p++) {
#pragma unroll
        for (int nt = 0; nt < 4; nt++) {
#pragma unroll
            for (int j = 0; j < 2; j++) {
                float v0 = acc[2 * p][nt][j],     v1 = acc[2 * p][nt][j + 2];
                float v2 = acc[2 * p + 1][nt][j], v3 = acc[2 * p + 1][nt][j + 2];
                float m = fmaxf(fmaxf(v0, v1), fmaxf(v2, v3));
                m = fmaxf(m, __shfl_xor_sync(0xffffffffu, m, 4));
                m = fmaxf(m, __shfl_xor_sync(0xffffffffu, m, 8));
                m = fmaxf(m, __shfl_xor_sync(0xffffffffu, m, 16));
                float e0 = __expf(v0 - m), e1 = __expf(v1 - m);
                float e2 = __expf(v2 - m), e3 = __expf(v3 - m);
                float s = e0 + e1 + e2 + e3;
                s += __shfl_xor_sync(0xffffffffu, s, 4);
                s += __shfl_xor_sync(0xffffffffu, s, 8);
                s += __shfl_xor_sync(0xffffffffu, s, 16);
                float inv = 1.0f / s;
                acc[2 * p][nt][j]         = e0 * inv;
                acc[2 * p][nt][j + 2]     = e1 * inv;
                acc[2 * p + 1][nt][j]     = e2 * inv;
                acc[2 * p + 1][nt][j + 2] = e3 * inv;
            }
        }
    }
#pragma unroll
    for (int mt = 0; mt < 4; mt++)
#pragma unroll
        for (int nt = 0; nt < 4; nt++)
#pragma unroll
            for (int j = 0; j < 4; j++)
                acc[mt][nt][j] = __uint_as_float(f2tf32(acc[mt][nt][j]));

#pragma unroll
    for (int mt = 0; mt < 4; mt++) {
        int r0 = m0 + wm * 64 + mt * 16 + g;   // <-- m0 restored (round-7 bug)
#pragma unroll
        for (int nt = 0; nt < 4; nt++) {
            int c = wn * 32 + nt * 8 + tg * 2;
            *(float2*)&ob[(size_t)r0 * HW_ + c]       = make_float2(acc[mt][nt][0], acc[mt][nt][1]);
            *(float2*)&ob[(size_t)(r0 + 8) * HW_ + c] = make_float2(acc[mt][nt][2], acc[mt][nt][3]);
        }
    }
}

// =====================================================================
// Kernel 2: fused kv GEMM + k-softmax + per-head context partial.
// grid (4 head-pairs, 32 pixel-tiles, 16 batches); 256 threads (8 warps 2x4).
// Zero-CVT mainloop, hoisted addressing, issue->commit->wait(1) pipeline.
// =====================================================================
__global__ void __launch_bounds__(256) k_kv_ctx() {
    extern __shared__ char smem_raw[];
    KvSmem& S = *reinterpret_cast<KvSmem*>(smem_raw);

    const int tid  = threadIdx.x;
    const int warp = tid >> 5, lane = tid & 31;
    const int g = lane >> 2, tg = lane & 3;
    const int wm = warp >> 2, wn = warp & 3;

    const int hp = blockIdx.x;
    const int pt = blockIdx.y;
    const int b  = blockIdx.z;
    const int p0 = pt * 128;

    const unsigned* xb = g_x + (size_t)b * (C_ * HW_) + p0;

    const unsigned* pa[4]; const unsigned* pb[4];
    unsigned sa[2][4], sb[2][4];
#pragma unroll
    for (int i = 0; i < 4; i++) {
        int f4 = tid + i * 256;
        int ra = f4 >> 3, ca = (f4 & 7) << 2;
        int gr = (ra < 64) ? (C_ + hp * 64 + ra) : (2 * C_ + hp * 64 + ra - 64);
        pa[i] = g_wq + (size_t)gr * C_ + ca;
        sa[0][i] = s2u(&S.u.gb.As[0][ra][ca]);
        sa[1][i] = s2u(&S.u.gb.As[1][ra][ca]);
        int rb = f4 >> 5, cb = (f4 & 31) << 2;
        pb[i] = xb + (size_t)rb * HW_ + cb;
        sb[0][i] = s2u(&S.u.gb.Bs[0][rb][cb]);
        sb[1][i] = s2u(&S.u.gb.Bs[1][rb][cb]);
    }

    float acc[4][4][4] = {};

#pragma unroll
    for (int i = 0; i < 4; i++) {
        cp16s(sa[0][i], pa[i]);  pa[i] += 32;
        cp16s(sb[0][i], pb[i]);  pb[i] += 32 * HW_;
    }
    CP_COMMIT();

    int buf = 0;
    for (int it = 0; it < 8; it++) {
        if (it < 7) {
#pragma unroll
            for (int i = 0; i < 4; i++) {
                cp16s(sa[buf ^ 1][i], pa[i]);  pa[i] += 32;
                cp16s(sb[buf ^ 1][i], pb[i]);  pb[i] += 32 * HW_;
            }
            CP_COMMIT();
            CP_WAIT(1);
        } else {
            CP_WAIT(0);
        }
        __syncthreads();
#pragma unroll
        for (int ks = 0; ks < 4; ks++) {
            const int kb = ks * 8;
            unsigned af[4][4], bf[4][2];
#pragma unroll
            for (int mt = 0; mt < 4; mt++) {
                int rm = wm * 64 + mt * 16;
                af[mt][0] = S.u.gb.As[buf][rm + g][kb + tg];
                af[mt][1] = S.u.gb.As[buf][rm + g + 8][kb + tg];
                af[mt][2] = S.u.gb.As[buf][rm + g][kb + tg + 4];
                af[mt][3] = S.u.gb.As[buf][rm + g + 8][kb + tg + 4];
            }
#pragma unroll
            for (int nt = 0; nt < 4; nt++) {
                int cn = wn * 32 + nt * 8 + g;
                bf[nt][0] = S.u.gb.Bs[buf][kb + tg][cn];
                bf[nt][1] = S.u.gb.Bs[buf][kb + tg + 4][cn];
            }
#pragma unroll
            for (int mt = 0; mt < 4; mt++)
#pragma unroll
                for (int nt = 0; nt < 4; nt++)
                    mma_tf32(acc[mt][nt], af[mt], bf[nt]);
        }
        __syncthreads();
        buf ^= 1;
    }

    // ---- k-softmax over y=64 (rows 0-63 -> wm==0 warps)
    float mloc[4][2], sloc[4][2];
    if (wm == 0) {
#pragma unroll
        for (int mt = 0; mt < 4; mt++)
#pragma unroll
            for (int hf = 0; hf < 2; hf++) {
                float m = -1e30f;
#pragma unroll
                for (int nt = 0; nt < 4; nt++) {
                    m = fmaxf(m, acc[mt][nt][hf * 2]);
                    m = fmaxf(m, acc[mt][nt][hf * 2 + 1]);
                }
                m = fmaxf(m, __shfl_xor_sync(0xffffffffu, m, 1));
                m = fmaxf(m, __shfl_xor_sync(0xffffffffu, m, 2));
                mloc[mt][hf] = m;
                if (tg == 0) S.red[0][wn][mt * 16 + hf * 8 + g] = m;
            }
    }
    __syncthreads();
    if (wm == 0) {
#pragma unroll
        for (int mt = 0; mt < 4; mt++)
#pragma unroll
            for (int hf = 0; hf < 2; hf++) {
                int ri = mt * 16 + hf * 8 + g;
                float m = fmaxf(mloc[mt][hf], S.red[0][wn ^ 1][ri]);
                float s = 0.f;
#pragma unroll
                for (int nt = 0; nt < 4; nt++) {
                    float e0 = __expf(acc[mt][nt][hf * 2] - m);
                    float e1 = __expf(acc[mt][nt][hf * 2 + 1] - m);
                    acc[mt][nt][hf * 2]     = e0;
                    acc[mt][nt][hf * 2 + 1] = e1;
                    s += e0 + e1;
                }
                s += __shfl_xor_sync(0xffffffffu, s, 1);
                s += __shfl_xor_sync(0xffffffffu, s, 2);
                sloc[mt][hf] = s;
                if (tg == 0) S.red[1][wn][ri] = s;
            }
    }
    __syncthreads();
    if (wm == 0) {
#pragma unroll
        for (int mt = 0; mt < 4; mt++)
#pragma unroll
            for (int hf = 0; hf < 2; hf++) {
                int ri = mt * 16 + hf * 8 + g;
                float inv = 1.0f / (sloc[mt][hf] + S.red[1][wn ^ 1][ri]);
#pragma unroll
                for (int nt = 0; nt < 4; nt++) {
                    acc[mt][nt][hf * 2]     *= inv;
                    acc[mt][nt][hf * 2 + 1] *= inv;
                }
            }
    }
    __syncthreads();   // mainloop reads done; safe to overlay sc

#pragma unroll
    for (int mt = 0; mt < 4; mt++) {
        int r0 = wm * 64 + mt * 16 + g;
#pragma unroll
        for (int nt = 0; nt < 4; nt++) {
            int c = wn * 32 + nt * 8 + tg * 2;
            S.u.sc[c][r0]         = acc[mt][nt][0];
            S.u.sc[c + 1][r0]     = acc[mt][nt][1];
            S.u.sc[c][r0 + 8]     = acc[mt][nt][2];
            S.u.sc[c + 1][r0 + 8] = acc[mt][nt][3];
        }
    }
    __syncthreads();

    // ctx partial per head: ctx[d][e] = sum_p khat[d][p] * v[e][p]  (fp32)
    {
        const int h  = tid >> 7;
        const int tl = tid & 127;
        const int td = tl >> 3;
        const int te = tl & 7;
        const int d0 = h * 32 + td * 2;
        const int e0 = 64 + h * 32 + te * 4;

        float a00 = 0.f, a01 = 0.f, a02 = 0.f, a03 = 0.f;
        float a10 = 0.f, a11 = 0.f, a12 = 0.f, a13 = 0.f;
#pragma unroll 8
        for (int p = 0; p < 128; p++) {
            float2 kk = *(const float2*)&S.u.sc[p][d0];
            float4 vv = *(const float4*)&S.u.sc[p][e0];
            a00 += kk.x * vv.x; a01 += kk.x * vv.y; a02 += kk.x * vv.z; a03 += kk.x * vv.w;
            a10 += kk.y * vv.x; a11 += kk.y * vv.y; a12 += kk.y * vv.z; a13 += kk.y * vv.w;
        }
        float* op = g_ctxp + (((size_t)(b * HEADS_ + hp * 2 + h)) * 32 + pt) * (D_ * D_);
        *(float4*)&op[(td * 2 + 0) * D_ + te * 4] = make_float4(a00, a01, a02, a03);
        *(float4*)&op[(td * 2 + 1) * D_ + te * 4] = make_float4(a10, a11, a12, a13);
    }
}

// =====================================================================
// Kernel 3: reduce ctx partials + w_eff = w_out(head slice) @ ctx (tf32 bits)
// =====================================================================
__global__ void __launch_bounds__(256) k_weff(const float* __restrict__ w_out) {
    const int h = blockIdx.x, b = blockIdx.y;
    const int bh = b * HEADS_ + h;
    const int t = threadIdx.x;

    __shared__ float ctxs[32][33];
    __shared__ float ws[256][33];

    const float* pp = g_ctxp + (size_t)bh * 32 * (D_ * D_);
#pragma unroll
    for (int i = 0; i < 4; i++) {
        int elem = t + i * 256;
        float s = 0.f;
#pragma unroll
        for (int pg = 0; pg < 32; pg++) s += pp[pg * (D_ * D_) + elem];
        ctxs[elem >> 5][elem & 31] = s;
    }
#pragma unroll
    for (int i = 0; i < 32; i++) {
        int idx = t + i * 256;
        int r = idx >> 5, c = idx & 31;
        ws[r][c] = w_out[(size_t)r * C_ + h * D_ + c];
    }
    __syncthreads();

    float we[32] = {};
#pragma unroll
    for (int d = 0; d < 32; d++) {
        float wv = ws[t][d];
#pragma unroll
        for (int e = 0; e < 32; e++) we[e] += wv * ctxs[d][e];
    }
    unsigned* op = g_weff + ((size_t)b * C_ + t) * C_ + h * D_;
#pragma unroll
    for (int e4 = 0; e4 < 8; e4++) {
        uint4 u = make_uint4(f2tf32(we[e4 * 4]), f2tf32(we[e4 * 4 + 1]),
                             f2tf32(we[e4 * 4 + 2]), f2tf32(we[e4 * 4 + 3]));
        *(uint4*)&op[e4 * 4] = u;
    }
}

// =====================================================================
// Kernel 4: out = w_eff[b] @ qhat + b_out, fused channel LayerNorm.
// Pre-tf32-bit operands, zero-CVT mainloop, hoisted addrs, wait(1) pipeline.
// =====================================================================
__global__ void __launch_bounds__(256) k_out_ln_tf32(const float* __restrict__ b_out,
                                                     const float* __restrict__ gamma,
                                                     const float* __restrict__ beta,
                                                     float* __restrict__ out) {
    extern __shared__ char smem_raw[];
    OutSmem& S = *reinterpret_cast<OutSmem*>(smem_raw);

    const int tid  = threadIdx.x;
    const int warp = tid >> 5, lane = tid & 31;
    const int g = lane >> 2, tg = lane & 3;
    const int wm = warp >> 1, wn = warp & 1;

    const int blk = blockIdx.x;
    const int b   = blk >> 6;
    const int p0  = (blk & 63) * 64;

    const float*    ab = g_q + (size_t)b * (C_ * HW_) + p0;   // qhat (tf32 bits)
    const unsigned* wb = g_weff + (size_t)b * C_ * C_;

    if (tid < 64) { S.s_sum[tid] = 0.f; S.s_sq[tid] = 0.f; }

    // hoisted pointers
    const unsigned* pa[8]; const float* pb[2];
    unsigned sa[2][8], sb[2][2];
#pragma unroll
    for (int i = 0; i < 8; i++) {
        int f4 = tid + i * 256;
        int ra = f4 >> 3, ca = (f4 & 7) << 2;
        pa[i] = wb + (size_t)ra * C_ + ca;
        sa[0][i] = s2u(&S.As[0][ra][ca]);
        sa[1][i] = s2u(&S.As[1][ra][ca]);
    }
#pragma unroll
    for (int i = 0; i < 2; i++) {
        int f4 = tid + i * 256;
        int rb = f4 >> 4, cb = (f4 & 15) << 2;
        pb[i] = ab + (size_t)rb * HW_ + cb;
        sb[0][i] = s2u(&S.Bs[0][rb][cb]);
        sb[1][i] = s2u(&S.Bs[1][rb][cb]);
    }

    float acc[4][4][4] = {};

#pragma unroll
    for (int i = 0; i < 8; i++) { cp16s(sa[0][i], pa[i]); pa[i] += 32; }
#pragma unroll
    for (int i = 0; i < 2; i++) { cp16s(sb[0][i], pb[i]); pb[i] += 32 * HW_; }
    CP_COMMIT();

    int buf = 0;
    for (int it = 0; it < 8; it++) {
        if (it < 7) {
#pragma unroll
            for (int i = 0; i < 8; i++) { cp16s(sa[buf ^ 1][i], pa[i]); pa[i] += 32; }
#pragma unroll
            for (int i = 0; i < 2; i++) { cp16s(sb[buf ^ 1][i], pb[i]); pb[i] += 32 * HW_; }
            CP_COMMIT();
            CP_WAIT(1);
        } else {
            CP_WAIT(0);
        }
        __syncthreads();

#pragma unroll
        for (int ks = 0; ks < 4; ks++) {
            const int kb = ks * 8;
            unsigned af[4][4], bf[4][2];
#pragma unroll
            for (int mt = 0; mt < 4; mt++) {
                int rm = wm * 64 + mt * 16;
                af[mt][0] = S.As[buf][rm + g][kb + tg];
                af[mt][1] = S.As[buf][rm + g + 8][kb + tg];
                af[mt][2] = S.As[buf][rm + g][kb + tg + 4];
                af[mt][3] = S.As[buf][rm + g + 8][kb + tg + 4];
            }
#pragma unroll
            for (int nt = 0; nt < 4; nt++) {
                int cn = wn * 32 + nt * 8 + g;
                bf[nt][0] = S.Bs[buf][kb + tg][cn];
                bf[nt][1] = S.Bs[buf][kb + tg + 4][cn];
            }
#pragma unroll
            for (int mt = 0; mt < 4; mt++)
#pragma unroll
                for (int nt = 0; nt < 4; nt++)
                    mma_tf32(acc[mt][nt], af[mt], bf[nt]);
        }
        __syncthreads();
        buf ^= 1;
    }

    float bias0[4], bias1[4], gam0[4], gam1[4], bet0[4], bet1[4];
#pragma unroll
    for (int mt = 0; mt < 4; mt++) {
        int r = wm * 64 + mt * 16 + g;
        bias0[mt] = b_out[r]; bias1[mt] = b_out[r + 8];
        gam0[mt]  = gamma[r]; gam1[mt]  = gamma[r + 8];
        bet0[mt]  = beta[r];  bet1[mt]  = beta[r + 8];
    }
#pragma unroll
    for (int mt = 0; mt < 4; mt++)
#pragma unroll
        for (int nt = 0; nt < 4; nt++) {
            acc[mt][nt][0] += bias0[mt]; acc[mt][nt][1] += bias0[mt];
            acc[mt][nt][2] += bias1[mt]; acc[mt][nt][3] += bias1[mt];
        }

#pragma unroll
    for (int nt = 0; nt < 4; nt++) {
        float s0 = 0.f, s1 = 0.f, q0 = 0.f, q1 = 0.f;
#pragma unroll
        for (int mt = 0; mt < 4; mt++) {
            float v0 = acc[mt][nt][0], v1 = acc[mt][nt][1];
            float v2 = acc[mt][nt][2], v3 = acc[mt][nt][3];
            s0 += v0 + v2; s1 += v1 + v3;
            q0 += v0 * v0 + v2 * v2; q1 += v1 * v1 + v3 * v3;
        }
#pragma unroll
        for (int off = 4; off < 32; off <<= 1) {
            s0 += __shfl_xor_sync(0xffffffffu, s0, off);
            s1 += __shfl_xor_sync(0xffffffffu, s1, off);
            q0 += __shfl_xor_sync(0xffffffffu, q0, off);
            q1 += __shfl_xor_sync(0xffffffffu, q1, off);
        }
        if (g == 0) {
            int c = wn * 32 + nt * 8 + tg * 2;
            atomicAdd(&S.s_sum[c], s0);     atomicAdd(&S.s_sq[c], q0);
            atomicAdd(&S.s_sum[c + 1], s1); atomicAdd(&S.s_sq[c + 1], q1);
        }
    }
    __syncthreads();

    if (tid < 64) {
        float mu  = S.s_sum[tid] * (1.0f / 256.0f);
        float var = S.s_sq[tid] * (1.0f / 256.0f) - mu * mu;
        S.s_mu[tid] = mu;
        S.s_rs[tid] = rsqrtf(var + LN_EPS);
    }
    __syncthreads();

    float* ob = out + (size_t)b * (C_ * HW_) + p0;
#pragma unroll
    for (int mt = 0; mt < 4; mt++) {
        int r = wm * 64 + mt * 16 + g;
#pragma unroll
        for (int nt = 0; nt < 4; nt++) {
            int c = wn * 32 + nt * 8 + tg * 2;
            float mu0 = S.s_mu[c], rs0 = S.s_rs[c];
            float mu1 = S.s_mu[c + 1], rs1 = S.s_rs[c + 1];
            float o0 = (acc[mt][nt][0] - mu0) * rs0 * gam0[mt] + bet0[mt];
            float o1 = (acc[mt][nt][1] - mu1) * rs1 * gam0[mt] + bet0[mt];
            float o2 = (acc[mt][nt][2] - mu0) * rs0 * gam1[mt] + bet1[mt];
            float o3 = (acc[mt][nt][3] - mu1) * rs1 * gam1[mt] + bet1[mt];
            *(float2*)&ob[(size_t)r * HW_ + c]       = make_float2(o0, o1);
            *(float2*)&ob[(size_t)(r + 8) * HW_ + c] = make_float2(o2, o3);
        }
    }
}

// =====================================================================
extern "C" void kernel_launch(void* const* d_in, const int* in_sizes, int n_in,
                              void* d_out, int out_size) {
    const float* x      = (const float*)d_in[0];
    const float* w_qkv  = (const float*)d_in[1];
    const float* w_out  = (const float*)d_in[2];
    const float* b_out  = (const float*)d_in[3];
    const float* gamma  = (const float*)d_in[4];
    const float* beta   = (const float*)d_in[5];
    float* out = (float*)d_out;

    cudaFuncSetAttribute(k_q_gemm, cudaFuncAttributeMaxDynamicSharedMemorySize,
                         (int)sizeof(GemmBufs));
    cudaFuncSetAttribute(k_kv_ctx, cudaFuncAttributeMaxDynamicSharedMemorySize,
                         (int)sizeof(KvSmem));
    cudaFuncSetAttribute(k_out_ln_tf32, cudaFuncAttributeMaxDynamicSharedMemorySize,
                         (int)sizeof(OutSmem));

    k_prex<<<(B_ * C_ * HW_) / 4 / 256, 256>>>(x);        // 16384 blocks
    k_prew<<<(3 * C_ * C_) / 4 / 256, 256>>>(w_qkv);      // 192 blocks

    dim3 g1((B_ * HW_) / 128, C_ / 128);                  // 512 x 2
    k_q_gemm<<<g1, 256, sizeof(GemmBufs)>>>();

    dim3 g2(4, 32, B_);                                   // head-pairs x tiles x batch
    k_kv_ctx<<<g2, 256, sizeof(KvSmem)>>>();

    dim3 g3(HEADS_, B_);                                  // 8 x 16
    k_weff<<<g3, 256>>>(w_out);

    k_out_ln_tf32<<<(B_ * HW_) / 64, 256, sizeof(OutSmem)>>>(b_out, gamma, beta, out);
}

// round 9
// speedup vs baseline: 1.1336x; 1.1138x over previous
#include <cuda_runtime.h>

// ---------------- problem constants ----------------
#define B_      16
#define C_      256
#define HEADS_  8
#define D_      32          // dim_head
#define HW_     4096        // 64*64
#define W_      64
#define LN_EPS  1e-5f

// ---------------- scratch (no allocations allowed) ----------------
__device__ unsigned g_wq[3 * C_ * C_];                 // w_qkv as tf32 bit patterns
__device__ float    g_q[(size_t)B_ * C_ * HW_];        // qhat as tf32 bit patterns
__device__ float    g_ctxp[(size_t)B_ * HEADS_ * 32 * (D_ * D_)];
__device__ unsigned g_weff[(size_t)B_ * C_ * C_];      // w_eff tf32 bits

// ---------------- helpers ----------------
__device__ __forceinline__ unsigned f2tf32(float f) {
    unsigned u;
    asm("cvt.rna.tf32.f32 %0, %1;" : "=r"(u) : "f"(f));
    return u;
}

__device__ __forceinline__ void mma_tf32(float* c, const unsigned* a, const unsigned* b) {
    asm volatile(
        "mma.sync.aligned.m16n8k8.row.col.f32.tf32.tf32.f32 "
        "{%0,%1,%2,%3}, {%4,%5,%6,%7}, {%8,%9}, {%0,%1,%2,%3};"
        : "+f"(c[0]), "+f"(c[1]), "+f"(c[2]), "+f"(c[3])
        : "r"(a[0]), "r"(a[1]), "r"(a[2]), "r"(a[3]), "r"(b[0]), "r"(b[1]));
}

__device__ __forceinline__ unsigned s2u(const void* p) {
    return (unsigned)__cvta_generic_to_shared(p);
}
__device__ __forceinline__ void cp16s(unsigned sdst, const void* gsrc) {
    asm volatile("cp.async.cg.shared.global [%0], [%1], 16;" :: "r"(sdst), "l"(gsrc));
}
#define CP_COMMIT()  asm volatile("cp.async.commit_group;")
#define CP_WAIT(n)   asm volatile("cp.async.wait_group %0;" :: "n"(n))

// ---------------- dynamic smem layouts ----------------
struct MainSmem {
    union {
        struct {
            unsigned As[2][128][36];   // [m][k] tf32 bits (from g_wq)
            float    Bs[2][32][136];   // [k][n] fp32 x-chunks
        } gb;
        unsigned sc[128][132];         // [pixel][row] khat|v as tf32 bits
    } u;
    float red[2][4][64];               // k-softmax cross-warp partials
    float P[8][32][33];                // per-warp ctx partials (pad 33)
};
struct OutSmem {
    unsigned As[2][256][36];
    unsigned Bs[2][32][72];
    float s_sum[64], s_sq[64], s_mu[64], s_rs[64];
};

// =====================================================================
// Kernel 0: pre-convert w_qkv to tf32 bit patterns (tiny)
// =====================================================================
__global__ void __launch_bounds__(256) k_prew(const float* __restrict__ w) {
    size_t i = (size_t)blockIdx.x * 256 + threadIdx.x;
    float4 v = ((const float4*)w)[i];
    uint4 u = make_uint4(f2tf32(v.x), f2tf32(v.y), f2tf32(v.z), f2tf32(v.w));
    ((uint4*)g_wq)[i] = u;
}

// =====================================================================
// Kernel 1 (MERGED): bid < 1024 -> q path: qhat = softmax_d(w_q @ x_tile)
//                    bid >= 1024 -> kv path: k-softmax + ctx partial (MMA)
// 256 threads (8 warps 2x4), 128x128x256 tile each.
// =====================================================================
__global__ void __launch_bounds__(256) k_main(const float* __restrict__ x) {
    extern __shared__ char smem_raw[];
    MainSmem& S = *reinterpret_cast<MainSmem*>(smem_raw);

    const int tid  = threadIdx.x;
    const int warp = tid >> 5, lane = tid & 31;
    const int g = lane >> 2, tg = lane & 3;
    const int wm = warp >> 2, wn = warp & 3;

    const int bid = blockIdx.x;
    const bool isQ = bid < 1024;
    int m0 = 0, b, p0, hp = 0, pt = 0;
    if (isQ) {
        m0 = (bid >> 9) * 128;
        int t = bid & 511;
        b  = t >> 5;
        p0 = (t & 31) * 128;
    } else {
        int k2 = bid - 1024;
        hp = k2 & 3;
        pt = (k2 >> 2) & 31;
        b  = k2 >> 7;
        p0 = pt * 128;
    }

    const float* xb = x + (size_t)b * (C_ * HW_) + p0;

    // hoisted per-thread load pointers + smem dst addresses
    const unsigned* pa[4]; const float* pb[4];
    unsigned sa[2][4], sb[2][4];
#pragma unroll
    for (int i = 0; i < 4; i++) {
        int f4 = tid + i * 256;
        int ra = f4 >> 3, ca = (f4 & 7) << 2;
        int gr = isQ ? (m0 + ra)
                     : ((ra < 64) ? (C_ + hp * 64 + ra) : (2 * C_ + hp * 64 + ra - 64));
        pa[i] = g_wq + (size_t)gr * C_ + ca;
        sa[0][i] = s2u(&S.u.gb.As[0][ra][ca]);
        sa[1][i] = s2u(&S.u.gb.As[1][ra][ca]);
        int rb = f4 >> 5, cb = (f4 & 31) << 2;
        pb[i] = xb + (size_t)rb * HW_ + cb;
        sb[0][i] = s2u(&S.u.gb.Bs[0][rb][cb]);
        sb[1][i] = s2u(&S.u.gb.Bs[1][rb][cb]);
    }

    float acc[4][4][4] = {};

    // prologue: chunk 0
#pragma unroll
    for (int i = 0; i < 4; i++) {
        cp16s(sa[0][i], pa[i]);  pa[i] += 32;
        cp16s(sb[0][i], pb[i]);  pb[i] += 32 * HW_;
    }
    CP_COMMIT();

    int buf = 0;
    for (int it = 0; it < 8; it++) {
        if (it < 7) {
#pragma unroll
            for (int i = 0; i < 4; i++) {
                cp16s(sa[buf ^ 1][i], pa[i]);  pa[i] += 32;
                cp16s(sb[buf ^ 1][i], pb[i]);  pb[i] += 32 * HW_;
            }
            CP_COMMIT();
            CP_WAIT(1);
        } else {
            CP_WAIT(0);
        }
        __syncthreads();
#pragma unroll
        for (int ks = 0; ks < 4; ks++) {
            const int kb = ks * 8;
            unsigned af[4][4], bf[4][2];
#pragma unroll
            for (int mt = 0; mt < 4; mt++) {
                int rm = wm * 64 + mt * 16;
                af[mt][0] = S.u.gb.As[buf][rm + g][kb + tg];
                af[mt][1] = S.u.gb.As[buf][rm + g + 8][kb + tg];
                af[mt][2] = S.u.gb.As[buf][rm + g][kb + tg + 4];
                af[mt][3] = S.u.gb.As[buf][rm + g + 8][kb + tg + 4];
            }
#pragma unroll
            for (int nt = 0; nt < 4; nt++) {
                int cn = wn * 32 + nt * 8 + g;
                bf[nt][0] = f2tf32(S.u.gb.Bs[buf][kb + tg][cn]);
                bf[nt][1] = f2tf32(S.u.gb.Bs[buf][kb + tg + 4][cn]);
            }
#pragma unroll
            for (int mt = 0; mt < 4; mt++)
#pragma unroll
                for (int nt = 0; nt < 4; nt++)
                    mma_tf32(acc[mt][nt], af[mt], bf[nt]);
        }
        __syncthreads();
        buf ^= 1;
    }

    if (isQ) {
        // ---- q-softmax over d=32 (head = mt-pair; rows span g via shfl)
#pragma unroll
        for (int p = 0; p < 2; p++) {
#pragma unroll
            for (int nt = 0; nt < 4; nt++) {
#pragma unroll
                for (int j = 0; j < 2; j++) {
                    float v0 = acc[2 * p][nt][j],     v1 = acc[2 * p][nt][j + 2];
                    float v2 = acc[2 * p + 1][nt][j], v3 = acc[2 * p + 1][nt][j + 2];
                    float m = fmaxf(fmaxf(v0, v1), fmaxf(v2, v3));
                    m = fmaxf(m, __shfl_xor_sync(0xffffffffu, m, 4));
                    m = fmaxf(m, __shfl_xor_sync(0xffffffffu, m, 8));
                    m = fmaxf(m, __shfl_xor_sync(0xffffffffu, m, 16));
                    float e0 = __expf(v0 - m), e1 = __expf(v1 - m);
                    float e2 = __expf(v2 - m), e3 = __expf(v3 - m);
                    float s = e0 + e1 + e2 + e3;
                    s += __shfl_xor_sync(0xffffffffu, s, 4);
                    s += __shfl_xor_sync(0xffffffffu, s, 8);
                    s += __shfl_xor_sync(0xffffffffu, s, 16);
                    float inv = 1.0f / s;
                    acc[2 * p][nt][j]         = e0 * inv;
                    acc[2 * p][nt][j + 2]     = e1 * inv;
                    acc[2 * p + 1][nt][j]     = e2 * inv;
                    acc[2 * p + 1][nt][j + 2] = e3 * inv;
                }
            }
        }
        float* ob = g_q + (size_t)b * (C_ * HW_) + p0;
#pragma unroll
        for (int mt = 0; mt < 4; mt++) {
            int r0 = m0 + wm * 64 + mt * 16 + g;
#pragma unroll
            for (int nt = 0; nt < 4; nt++) {
                int c = wn * 32 + nt * 8 + tg * 2;
                float q0 = __uint_as_float(f2tf32(acc[mt][nt][0]));
                float q1 = __uint_as_float(f2tf32(acc[mt][nt][1]));
                float q2 = __uint_as_float(f2tf32(acc[mt][nt][2]));
                float q3 = __uint_as_float(f2tf32(acc[mt][nt][3]));
                *(float2*)&ob[(size_t)r0 * HW_ + c]       = make_float2(q0, q1);
                *(float2*)&ob[(size_t)(r0 + 8) * HW_ + c] = make_float2(q2, q3);
            }
        }
        return;
    }

    // ================= kv path =================
    // ---- k-softmax over y=64 (rows 0-63 -> wm==0 warps)
    float mloc[4][2], sloc[4][2];
    if (wm == 0) {
#pragma unroll
        for (int mt = 0; mt < 4; mt++)
#pragma unroll
            for (int hf = 0; hf < 2; hf++) {
                float m = -1e30f;
#pragma unroll
                for (int nt = 0; nt < 4; nt++) {
                    m = fmaxf(m, acc[mt][nt][hf * 2]);
                    m = fmaxf(m, acc[mt][nt][hf * 2 + 1]);
                }
                m = fmaxf(m, __shfl_xor_sync(0xffffffffu, m, 1));
                m = fmaxf(m, __shfl_xor_sync(0xffffffffu, m, 2));
                mloc[mt][hf] = m;
                if (tg == 0) S.red[0][wn][mt * 16 + hf * 8 + g] = m;
            }
    }
    __syncthreads();
    if (wm == 0) {
#pragma unroll
        for (int mt = 0; mt < 4; mt++)
#pragma unroll
            for (int hf = 0; hf < 2; hf++) {
                int ri = mt * 16 + hf * 8 + g;
                float m = fmaxf(mloc[mt][hf], S.red[0][wn ^ 1][ri]);
                float s = 0.f;
#pragma unroll
                for (int nt = 0; nt < 4; nt++) {
                    float e0 = __expf(acc[mt][nt][hf * 2] - m);
                    float e1 = __expf(acc[mt][nt][hf * 2 + 1] - m);
                    acc[mt][nt][hf * 2]     = e0;
                    acc[mt][nt][hf * 2 + 1] = e1;
                    s += e0 + e1;
                }
                s += __shfl_xor_sync(0xffffffffu, s, 1);
                s += __shfl_xor_sync(0xffffffffu, s, 2);
                sloc[mt][hf] = s;
                if (tg == 0) S.red[1][wn][ri] = s;
            }
    }
    __syncthreads();
    if (wm == 0) {
#pragma unroll
        for (int mt = 0; mt < 4; mt++)
#pragma unroll
            for (int hf = 0; hf < 2; hf++) {
                int ri = mt * 16 + hf * 8 + g;
                float inv = 1.0f / (sloc[mt][hf] + S.red[1][wn ^ 1][ri]);
#pragma unroll
                for (int nt = 0; nt < 4; nt++) {
                    acc[mt][nt][hf * 2]     *= inv;
                    acc[mt][nt][hf * 2 + 1] *= inv;
                }
            }
    }
    __syncthreads();   // mainloop smem reads done; safe to overlay sc

    // ---- store transposed [pixel][row] as tf32 bits (banks 4tg+g bijective)
#pragma unroll
    for (int mt = 0; mt < 4; mt++) {
        int r0 = wm * 64 + mt * 16 + g;
#pragma unroll
        for (int nt = 0; nt < 4; nt++) {
            int c = wn * 32 + nt * 8 + tg * 2;
            S.u.sc[c][r0]         = f2tf32(acc[mt][nt][0]);
            S.u.sc[c + 1][r0]     = f2tf32(acc[mt][nt][1]);
            S.u.sc[c][r0 + 8]     = f2tf32(acc[mt][nt][2]);
            S.u.sc[c + 1][r0 + 8] = f2tf32(acc[mt][nt][3]);
        }
    }
    __syncthreads();

    // ---- ctx partial via tensor cores: per warp M=32(d) x N=32(e) x K=32(p)
    // warp 0-3: head 0, K slices 0-3; warp 4-7: head 1, K slices 0-3.
    {
        const int h  = warp >> 2, hb = h * 32;
        const int pb0 = (warp & 3) * 32;
        float cacc[2][4][4] = {};
#pragma unroll
        for (int ks = 0; ks < 4; ks++) {
            const int kb = pb0 + ks * 8;
            unsigned af[2][4], bf[4][2];
#pragma unroll
            for (int mt = 0; mt < 2; mt++) {
                int dm = hb + mt * 16 + g;
                af[mt][0] = S.u.sc[kb + tg][dm];
                af[mt][1] = S.u.sc[kb + tg][dm + 8];
                af[mt][2] = S.u.sc[kb + tg + 4][dm];
                af[mt][3] = S.u.sc[kb + tg + 4][dm + 8];
            }
#pragma unroll
            for (int nt = 0; nt < 4; nt++) {
                int en = 64 + hb + nt * 8 + g;
                bf[nt][0] = S.u.sc[kb + tg][en];
                bf[nt][1] = S.u.sc[kb + tg + 4][en];
            }
#pragma unroll
            for (int mt = 0; mt < 2; mt++)
#pragma unroll
                for (int nt = 0; nt < 4; nt++)
                    mma_tf32(cacc[mt][nt], af[mt], bf[nt]);
        }
        // write warp partial P[warp][d][e]
#pragma unroll
        for (int mt = 0; mt < 2; mt++) {
            int d = mt * 16 + g;
#pragma unroll
            for (int nt = 0; nt < 4; nt++) {
                int e = nt * 8 + tg * 2;
                S.P[warp][d][e]         = cacc[mt][nt][0];
                S.P[warp][d][e + 1]     = cacc[mt][nt][1];
                S.P[warp][d + 8][e]     = cacc[mt][nt][2];
                S.P[warp][d + 8][e + 1] = cacc[mt][nt][3];
            }
        }
    }
    __syncthreads();

    // ---- reduce 4 K-slices per head, write ctx partial to gmem
    {
        float* op = g_ctxp + (((size_t)(b * HEADS_ + hp * 2)) * 32 + pt) * (D_ * D_);
#pragma unroll
        for (int i = 0; i < 8; i++) {
            int elem = tid + i * 256;          // 0..2047 (2 heads x 1024)
            int hh = elem >> 10;
            int de = elem & 1023;
            int d = de >> 5, e = de & 31;
            float s = S.P[hh * 4 + 0][d][e] + S.P[hh * 4 + 1][d][e]
                    + S.P[hh * 4 + 2][d][e] + S.P[hh * 4 + 3][d][e];
            op[(size_t)hh * 32 * (D_ * D_) + de] = s;
        }
    }
}

// =====================================================================
// Kernel 2: reduce ctx partials + w_eff = w_out(head slice) @ ctx (tf32 bits)
// =====================================================================
__global__ void __launch_bounds__(256) k_weff(const float* __restrict__ w_out) {
    const int h = blockIdx.x, b = blockIdx.y;
    const int bh = b * HEADS_ + h;
    const int t = threadIdx.x;

    __shared__ float ctxs[32][33];
    __shared__ float ws[256][33];

    const float* pp = g_ctxp + (size_t)bh * 32 * (D_ * D_);
#pragma unroll
    for (int i = 0; i < 4; i++) {
        int elem = t + i * 256;
        float s = 0.f;
#pragma unroll
        for (int pg = 0; pg < 32; pg++) s += pp[pg * (D_ * D_) + elem];
        ctxs[elem >> 5][elem & 31] = s;
    }
#pragma unroll
    for (int i = 0; i < 32; i++) {
        int idx = t + i * 256;
        int r = idx >> 5, c = idx & 31;
        ws[r][c] = w_out[(size_t)r * C_ + h * D_ + c];
    }
    __syncthreads();

    float we[32] = {};
#pragma unroll
    for (int d = 0; d < 32; d++) {
        float wv = ws[t][d];
#pragma unroll
        for (int e = 0; e < 32; e++) we[e] += wv * ctxs[d][e];
    }
    unsigned* op = g_weff + ((size_t)b * C_ + t) * C_ + h * D_;
#pragma unroll
    for (int e4 = 0; e4 < 8; e4++) {
        uint4 u = make_uint4(f2tf32(we[e4 * 4]), f2tf32(we[e4 * 4 + 1]),
                             f2tf32(we[e4 * 4 + 2]), f2tf32(we[e4 * 4 + 3]));
        *(uint4*)&op[e4 * 4] = u;
    }
}

// =====================================================================
// Kernel 3: out = w_eff[b] @ qhat + b_out, fused channel LayerNorm.
// =====================================================================
__global__ void __launch_bounds__(256) k_out_ln_tf32(const float* __restrict__ b_out,
                                                     const float* __restrict__ gamma,
                                                     const float* __restrict__ beta,
                                                     float* __restrict__ out) {
    extern __shared__ char smem_raw[];
    OutSmem& S = *reinterpret_cast<OutSmem*>(smem_raw);

    const int tid  = threadIdx.x;
    const int warp = tid >> 5, lane = tid & 31;
    const int g = lane >> 2, tg = lane & 3;
    const int wm = warp >> 1, wn = warp & 1;

    const int blk = blockIdx.x;
    const int b   = blk >> 6;
    const int p0  = (blk & 63) * 64;

    const float*    ab = g_q + (size_t)b * (C_ * HW_) + p0;   // qhat (tf32 bits)
    const unsigned* wb = g_weff + (size_t)b * C_ * C_;

    if (tid < 64) { S.s_sum[tid] = 0.f; S.s_sq[tid] = 0.f; }

    const unsigned* pa[8]; const float* pb[2];
    unsigned sa[2][8], sb[2][2];
#pragma unroll
    for (int i = 0; i < 8; i++) {
        int f4 = tid + i * 256;
        int ra = f4 >> 3, ca = (f4 & 7) << 2;
        pa[i] = wb + (size_t)ra * C_ + ca;
        sa[0][i] = s2u(&S.As[0][ra][ca]);
        sa[1][i] = s2u(&S.As[1][ra][ca]);
    }
#pragma unroll
    for (int i = 0; i < 2; i++) {
        int f4 = tid + i * 256;
        int rb = f4 >> 4, cb = (f4 & 15) << 2;
        pb[i] = ab + (size_t)rb * HW_ + cb;
        sb[0][i] = s2u(&S.Bs[0][rb][cb]);
        sb[1][i] = s2u(&S.Bs[1][rb][cb]);
    }

    float acc[4][4][4] = {};

#pragma unroll
    for (int i = 0; i < 8; i++) { cp16s(sa[0][i], pa[i]); pa[i] += 32; }
#pragma unroll
    for (int i = 0; i < 2; i++) { cp16s(sb[0][i], pb[i]); pb[i] += 32 * HW_; }
    CP_COMMIT();

    int buf = 0;
    for (int it = 0; it < 8; it++) {
        if (it < 7) {
#pragma unroll
            for (int i = 0; i < 8; i++) { cp16s(sa[buf ^ 1][i], pa[i]); pa[i] += 32; }
#pragma unroll
            for (int i = 0; i < 2; i++) { cp16s(sb[buf ^ 1][i], pb[i]); pb[i] += 32 * HW_; }
            CP_COMMIT();
            CP_WAIT(1);
        } else {
            CP_WAIT(0);
        }
        __syncthreads();

#pragma unroll
        for (int ks = 0; ks < 4; ks++) {
            const int kb = ks * 8;
            unsigned af[4][4], bf[4][2];
#pragma unroll
            for (int mt = 0; mt < 4; mt++) {
                int rm = wm * 64 + mt * 16;
                af[mt][0] = S.As[buf][rm + g][kb + tg];
                af[mt][1] = S.As[buf][rm + g + 8][kb + tg];
                af[mt][2] = S.As[buf][rm + g][kb + tg + 4];
                af[mt][3] = S.As[buf][rm + g + 8][kb + tg + 4];
            }
#pragma unroll
            for (int nt = 0; nt < 4; nt++) {
                int cn = wn * 32 + nt * 8 + g;
                bf[nt][0] = S.Bs[buf][kb + tg][cn];
                bf[nt][1] = S.Bs[buf][kb + tg + 4][cn];
            }
#pragma unroll
            for (int mt = 0; mt < 4; mt++)
#pragma unroll
                for (int nt = 0; nt < 4; nt++)
                    mma_tf32(acc[mt][nt], af[mt], bf[nt]);
        }
        __syncthreads();
        buf ^= 1;
    }

    float bias0[4], bias1[4], gam0[4], gam1[4], bet0[4], bet1[4];
#pragma unroll
    for (int mt = 0; mt < 4; mt++) {
        int r = wm * 64 + mt * 16 + g;
        bias0[mt] = b_out[r]; bias1[mt] = b_out[r + 8];
        gam0[mt]  = gamma[r]; gam1[mt]  = gamma[r + 8];
        bet0[mt]  = beta[r];  bet1[mt]  = beta[r + 8];
    }
#pragma unroll
    for (int mt = 0; mt < 4; mt++)
#pragma unroll
        for (int nt = 0; nt < 4; nt++) {
            acc[mt][nt][0] += bias0[mt]; acc[mt][nt][1] += bias0[mt];
            acc[mt][nt][2] += bias1[mt]; acc[mt][nt][3] += bias1[mt];
        }

#pragma unroll
    for (int nt = 0; nt < 4; nt++) {
        float s0 = 0.f, s1 = 0.f, q0 = 0.f, q1 = 0.f;
#pragma unroll
        for (int mt = 0; mt < 4; mt++) {
            float v0 = acc[mt][nt][0], v1 = acc[mt][nt][1];
            float v2 = acc[mt][nt][2], v3 = acc[mt][nt][3];
            s0 += v0 + v2; s1 += v1 + v3;
            q0 += v0 * v0 + v2 * v2; q1 += v1 * v1 + v3 * v3;
        }
#pragma unroll
        for (int off = 4; off < 32; off <<= 1) {
            s0 += __shfl_xor_sync(0xffffffffu, s0, off);
            s1 += __shfl_xor_sync(0xffffffffu, s1, off);
            q0 += __shfl_xor_sync(0xffffffffu, q0, off);
            q1 += __shfl_xor_sync(0xffffffffu, q1, off);
        }
        if (g == 0) {
            int c = wn * 32 + nt * 8 + tg * 2;
            atomicAdd(&S.s_sum[c], s0);     atomicAdd(&S.s_sq[c], q0);
            atomicAdd(&S.s_sum[c + 1], s1); atomicAdd(&S.s_sq[c + 1], q1);
        }
    }
    __syncthreads();

    if (tid < 64) {
        float mu  = S.s_sum[tid] * (1.0f / 256.0f);
        float var = S.s_sq[tid] * (1.0f / 256.0f) - mu * mu;
        S.s_mu[tid] = mu;
        S.s_rs[tid] = rsqrtf(var + LN_EPS);
    }
    __syncthreads();

    float* ob = out + (size_t)b * (C_ * HW_) + p0;
#pragma unroll
    for (int mt = 0; mt < 4; mt++) {
        int r = wm * 64 + mt * 16 + g;
#pragma unroll
        for (int nt = 0; nt < 4; nt++) {
            int c = wn * 32 + nt * 8 + tg * 2;
            float mu0 = S.s_mu[c], rs0 = S.s_rs[c];
            float mu1 = S.s_mu[c + 1], rs1 = S.s_rs[c + 1];
            float o0 = (acc[mt][nt][0] - mu0) * rs0 * gam0[mt] + bet0[mt];
            float o1 = (acc[mt][nt][1] - mu1) * rs1 * gam0[mt] + bet0[mt];
            float o2 = (acc[mt][nt][2] - mu0) * rs0 * gam1[mt] + bet1[mt];
            float o3 = (acc[mt][nt][3] - mu1) * rs1 * gam1[mt] + bet1[mt];
            *(float2*)&ob[(size_t)r * HW_ + c]       = make_float2(o0, o1);
            *(float2*)&ob[(size_t)(r + 8) * HW_ + c] = make_float2(o2, o3);
        }
    }
}

// =====================================================================
extern "C" void kernel_launch(void* const* d_in, const int* in_sizes, int n_in,
                              void* d_out, int out_size) {
    const float* x      = (const float*)d_in[0];
    const float* w_qkv  = (const float*)d_in[1];
    const float* w_out  = (const float*)d_in[2];
    const float* b_out  = (const float*)d_in[3];
    const float* gamma  = (const float*)d_in[4];
    const float* beta   = (const float*)d_in[5];
    float* out = (float*)d_out;

    cudaFuncSetAttribute(k_main, cudaFuncAttributeMaxDynamicSharedMemorySize,
                         (int)sizeof(MainSmem));
    cudaFuncSetAttribute(k_out_ln_tf32, cudaFuncAttributeMaxDynamicSharedMemorySize,
                         (int)sizeof(OutSmem));

    k_prew<<<(3 * C_ * C_) / 4 / 256, 256>>>(w_qkv);      // 192 blocks

    k_main<<<1024 + 2048, 256, sizeof(MainSmem)>>>(x);    // q blocks first, then kv

    dim3 g3(HEADS_, B_);                                  // 8 x 16
    k_weff<<<g3, 256>>>(w_out);

    k_out_ln_tf32<<<(B_ * HW_) / 64, 256, sizeof(OutSmem)>>>(b_out, gamma, beta, out);
}

// round 10
// speedup vs baseline: 1.4607x; 1.2886x over previous
#include <cuda_runtime.h>
#include <cuda_fp16.h>

// ---------------- problem constants ----------------
#define B_      16
#define C_      256
#define HEADS_  8
#define D_      32          // dim_head
#define HW_     4096        // 64*64
#define W_      64
#define LN_EPS  1e-5f

// ---------------- scratch (no allocations allowed) ----------------
__device__ __half  g_wqh[3 * C_ * C_];                    // w_qkv fp16
__device__ __half2 g_xh[(size_t)B_ * 128 * HW_];          // x packed [b][c2][p]
__device__ __half2 g_q2[(size_t)B_ * 128 * HW_];          // qhat packed [b][c2][p]
__device__ float   g_ctxp[(size_t)B_ * HEADS_ * 32 * (D_ * D_)];
__device__ __half  g_weffh[(size_t)B_ * C_ * C_];         // w_eff fp16

// ---------------- helpers ----------------
__device__ __forceinline__ unsigned h2u(__half2 h) { return *(unsigned*)&h; }

__device__ __forceinline__ void mma_f16(float* c, const unsigned* a, const unsigned* b) {
    asm volatile(
        "mma.sync.aligned.m16n8k16.row.col.f32.f16.f16.f32 "
        "{%0,%1,%2,%3}, {%4,%5,%6,%7}, {%8,%9}, {%0,%1,%2,%3};"
        : "+f"(c[0]), "+f"(c[1]), "+f"(c[2]), "+f"(c[3])
        : "r"(a[0]), "r"(a[1]), "r"(a[2]), "r"(a[3]), "r"(b[0]), "r"(b[1]));
}

__device__ __forceinline__ unsigned s2u(const void* p) {
    return (unsigned)__cvta_generic_to_shared(p);
}
__device__ __forceinline__ void cp16s(unsigned sdst, const void* gsrc) {
    asm volatile("cp.async.cg.shared.global [%0], [%1], 16;" :: "r"(sdst), "l"(gsrc));
}
#define CP_COMMIT()  asm volatile("cp.async.commit_group;")
#define CP_WAIT(n)   asm volatile("cp.async.wait_group %0;" :: "n"(n))

// ---------------- dynamic smem layouts ----------------
struct MainSmem {
    union {
        struct {
            __half  As[2][128][40];    // [m][k] halves, pad 40 -> banks 20g+tg bijective
            __half2 Bs[2][16][136];    // [k2][pixel] chan-pairs, pad 136 -> 8tg+g
        } ld;
        float P[8][32][33];            // per-warp ctx partials (dead-As/Bs overlay)
    } u;
    __half sc[128][136];               // [row][pixel] khat|v halves
    float red[2][4][64];               // k-softmax cross-warp partials
};
struct OutSmem {
    __half  As[2][256][40];
    __half2 Bs[2][16][72];             // pad 72 -> 8tg+g bijective
    float s_sum[64], s_sq[64], s_mu[64], s_rs[64];
};

// =====================================================================
// Kernel 0a: pack x -> fp16 [b][c2][p] half2 (chan 2c2, 2c2+1 per pixel)
// =====================================================================
__global__ void __launch_bounds__(256) k_prex(const float* __restrict__ x) {
    unsigned i = blockIdx.x * 256 + threadIdx.x;     // (b, c2, p4)
    int p4 = i & 1023;
    int c2 = (i >> 10) & 127;
    int b  = i >> 17;
    const float4 v0 = *(const float4*)&x[((size_t)b * C_ + 2 * c2)     * HW_ + p4 * 4];
    const float4 v1 = *(const float4*)&x[((size_t)b * C_ + 2 * c2 + 1) * HW_ + p4 * 4];
    __half2* dst = &g_xh[((size_t)b * 128 + c2) * HW_ + p4 * 4];
    dst[0] = __floats2half2_rn(v0.x, v1.x);
    dst[1] = __floats2half2_rn(v0.y, v1.y);
    dst[2] = __floats2half2_rn(v0.z, v1.z);
    dst[3] = __floats2half2_rn(v0.w, v1.w);
}

// Kernel 0b: w_qkv -> fp16 (row-major, natural K-pairing for A operand)
__global__ void __launch_bounds__(256) k_prew(const float* __restrict__ w) {
    unsigned i = blockIdx.x * 256 + threadIdx.x;
    float4 v = ((const float4*)w)[i];
    __half2* dst = (__half2*)&g_wqh[(size_t)i * 4];
    dst[0] = __floats2half2_rn(v.x, v.y);
    dst[1] = __floats2half2_rn(v.z, v.w);
}

// =====================================================================
// Kernel 1 (MERGED): bid < 1024 -> q path; bid >= 1024 -> kv+ctx path.
// fp16 m16n8k16, 128x128x256 tiles, 8 warps (2x4), fp32 accumulate.
// =====================================================================
__global__ void __launch_bounds__(256) k_main() {
    extern __shared__ char smem_raw[];
    MainSmem& S = *reinterpret_cast<MainSmem*>(smem_raw);

    const int tid  = threadIdx.x;
    const int warp = tid >> 5, lane = tid & 31;
    const int g = lane >> 2, tg = lane & 3;
    const int wm = warp >> 2, wn = warp & 3;

    const int bid = blockIdx.x;
    const bool isQ = bid < 1024;
    int m0 = 0, b, p0, hp = 0, pt = 0;
    if (isQ) {
        m0 = (bid >> 9) * 128;
        int t = bid & 511;
        b  = t >> 5;
        p0 = (t & 31) * 128;
    } else {
        int k2 = bid - 1024;
        hp = k2 & 3;
        pt = (k2 >> 2) & 31;
        b  = k2 >> 7;
        p0 = pt * 128;
    }

    // hoisted pointers: A (w rows, halves), B (g_xh half2)
    const __half* pa[2]; const __half2* pb[2];
    unsigned sa[2][2], sb[2][2];
#pragma unroll
    for (int i = 0; i < 2; i++) {
        int f4 = tid + i * 256;
        int ra = f4 >> 2, ca = (f4 & 3) * 8;         // 128 rows x 32 halves
        int gr = isQ ? (m0 + ra)
                     : ((ra < 64) ? (C_ + hp * 64 + ra) : (2 * C_ + hp * 64 + ra - 64));
        pa[i] = g_wqh + (size_t)gr * C_ + ca;
        sa[0][i] = s2u(&S.u.ld.As[0][ra][ca]);
        sa[1][i] = s2u(&S.u.ld.As[1][ra][ca]);
        int rb = f4 >> 5, cb = (f4 & 31) * 4;        // 16 c2-rows x 128 half2
        pb[i] = g_xh + ((size_t)b * 128 + rb) * HW_ + p0 + cb;
        sb[0][i] = s2u(&S.u.ld.Bs[0][rb][cb]);
        sb[1][i] = s2u(&S.u.ld.Bs[1][rb][cb]);
    }

    float acc[4][4][4] = {};

#pragma unroll
    for (int i = 0; i < 2; i++) {
        cp16s(sa[0][i], pa[i]);  pa[i] += 32;
        cp16s(sb[0][i], pb[i]);  pb[i] += 16 * HW_;
    }
    CP_COMMIT();

    int buf = 0;
    for (int it = 0; it < 8; it++) {
        if (it < 7) {
#pragma unroll
            for (int i = 0; i < 2; i++) {
                cp16s(sa[buf ^ 1][i], pa[i]);  pa[i] += 32;
                cp16s(sb[buf ^ 1][i], pb[i]);  pb[i] += 16 * HW_;
            }
            CP_COMMIT();
            CP_WAIT(1);
        } else {
            CP_WAIT(0);
        }
        __syncthreads();
#pragma unroll
        for (int ks = 0; ks < 2; ks++) {
            const int kA = ks * 16;                  // halves
            unsigned af[4][4], bf[4][2];
#pragma unroll
            for (int mt = 0; mt < 4; mt++) {
                int rm = wm * 64 + mt * 16;
                af[mt][0] = *(const unsigned*)&S.u.ld.As[buf][rm + g][kA + 2 * tg];
                af[mt][1] = *(const unsigned*)&S.u.ld.As[buf][rm + g + 8][kA + 2 * tg];
                af[mt][2] = *(const unsigned*)&S.u.ld.As[buf][rm + g][kA + 2 * tg + 8];
                af[mt][3] = *(const unsigned*)&S.u.ld.As[buf][rm + g + 8][kA + 2 * tg + 8];
            }
#pragma unroll
            for (int nt = 0; nt < 4; nt++) {
                int cn = wn * 32 + nt * 8 + g;
                bf[nt][0] = h2u(S.u.ld.Bs[buf][ks * 8 + tg][cn]);
                bf[nt][1] = h2u(S.u.ld.Bs[buf][ks * 8 + tg + 4][cn]);
            }
#pragma unroll
            for (int mt = 0; mt < 4; mt++)
#pragma unroll
                for (int nt = 0; nt < 4; nt++)
                    mma_f16(acc[mt][nt], af[mt], bf[nt]);
        }
        __syncthreads();
        buf ^= 1;
    }

    if (isQ) {
        // ---- q-softmax over d=32 (head = mt-pair; rows span g via shfl)
#pragma unroll
        for (int p = 0; p < 2; p++) {
#pragma unroll
            for (int nt = 0; nt < 4; nt++) {
#pragma unroll
                for (int j = 0; j < 2; j++) {
                    float v0 = acc[2 * p][nt][j],     v1 = acc[2 * p][nt][j + 2];
                    float v2 = acc[2 * p + 1][nt][j], v3 = acc[2 * p + 1][nt][j + 2];
                    float m = fmaxf(fmaxf(v0, v1), fmaxf(v2, v3));
                    m = fmaxf(m, __shfl_xor_sync(0xffffffffu, m, 4));
                    m = fmaxf(m, __shfl_xor_sync(0xffffffffu, m, 8));
                    m = fmaxf(m, __shfl_xor_sync(0xffffffffu, m, 16));
                    float e0 = __expf(v0 - m), e1 = __expf(v1 - m);
                    float e2 = __expf(v2 - m), e3 = __expf(v3 - m);
                    float s = e0 + e1 + e2 + e3;
                    s += __shfl_xor_sync(0xffffffffu, s, 4);
                    s += __shfl_xor_sync(0xffffffffu, s, 8);
                    s += __shfl_xor_sync(0xffffffffu, s, 16);
                    float inv = 1.0f / s;
                    acc[2 * p][nt][j]         = e0 * inv;
                    acc[2 * p][nt][j + 2]     = e1 * inv;
                    acc[2 * p + 1][nt][j]     = e2 * inv;
                    acc[2 * p + 1][nt][j + 2] = e3 * inv;
                }
            }
        }
        // ---- paired fp16 store: channel pairs (r0, r0+1) via shfl_xor(4)
#pragma unroll
        for (int mt = 0; mt < 4; mt++) {
            int r0 = m0 + wm * 64 + mt * 16 + g;
#pragma unroll
            for (int nt = 0; nt < 4; nt++) {
                float o0 = acc[mt][nt][0], o1 = acc[mt][nt][1];
                float o2 = acc[mt][nt][2], o3 = acc[mt][nt][3];
                float q0 = __shfl_xor_sync(0xffffffffu, o0, 4);
                float q1 = __shfl_xor_sync(0xffffffffu, o1, 4);
                float q2 = __shfl_xor_sync(0xffffffffu, o2, 4);
                float q3 = __shfl_xor_sync(0xffffffffu, o3, 4);
                if (!(g & 1)) {
                    int c = wn * 32 + nt * 8 + tg * 2;
                    __half2* d0 = &g_q2[((size_t)b * 128 + (r0 >> 1)) * HW_ + p0 + c];
                    d0[0] = __floats2half2_rn(o0, q0);
                    d0[1] = __floats2half2_rn(o1, q1);
                    __half2* d1 = d0 + (size_t)4 * HW_;     // rows r0+8, r0+9
                    d1[0] = __floats2half2_rn(o2, q2);
                    d1[1] = __floats2half2_rn(o3, q3);
                }
            }
        }
        return;
    }

    // ================= kv path =================
    // ---- k-softmax over y=64 (rows 0-63 -> wm==0 warps)
    float mloc[4][2], sloc[4][2];
    if (wm == 0) {
#pragma unroll
        for (int mt = 0; mt < 4; mt++)
#pragma unroll
            for (int hf = 0; hf < 2; hf++) {
                float m = -1e30f;
#pragma unroll
                for (int nt = 0; nt < 4; nt++) {
                    m = fmaxf(m, acc[mt][nt][hf * 2]);
                    m = fmaxf(m, acc[mt][nt][hf * 2 + 1]);
                }
                m = fmaxf(m, __shfl_xor_sync(0xffffffffu, m, 1));
                m = fmaxf(m, __shfl_xor_sync(0xffffffffu, m, 2));
                mloc[mt][hf] = m;
                if (tg == 0) S.red[0][wn][mt * 16 + hf * 8 + g] = m;
            }
    }
    __syncthreads();
    if (wm == 0) {
#pragma unroll
        for (int mt = 0; mt < 4; mt++)
#pragma unroll
            for (int hf = 0; hf < 2; hf++) {
                int ri = mt * 16 + hf * 8 + g;
                float m = fmaxf(mloc[mt][hf], S.red[0][wn ^ 1][ri]);
                float s = 0.f;
#pragma unroll
                for (int nt = 0; nt < 4; nt++) {
                    float e0 = __expf(acc[mt][nt][hf * 2] - m);
                    float e1 = __expf(acc[mt][nt][hf * 2 + 1] - m);
                    acc[mt][nt][hf * 2]     = e0;
                    acc[mt][nt][hf * 2 + 1] = e1;
                    s += e0 + e1;
                }
                s += __shfl_xor_sync(0xffffffffu, s, 1);
                s += __shfl_xor_sync(0xffffffffu, s, 2);
                sloc[mt][hf] = s;
                if (tg == 0) S.red[1][wn][ri] = s;
            }
    }
    __syncthreads();
    if (wm == 0) {
#pragma unroll
        for (int mt = 0; mt < 4; mt++)
#pragma unroll
            for (int hf = 0; hf < 2; hf++) {
                int ri = mt * 16 + hf * 8 + g;
                float inv = 1.0f / (sloc[mt][hf] + S.red[1][wn ^ 1][ri]);
#pragma unroll
                for (int nt = 0; nt < 4; nt++) {
                    acc[mt][nt][hf * 2]     *= inv;
                    acc[mt][nt][hf * 2 + 1] *= inv;
                }
            }
    }
    __syncthreads();

    // ---- store sc[row][pixel] as fp16 (half2 per pixel pair)
#pragma unroll
    for (int mt = 0; mt < 4; mt++) {
        int r0 = wm * 64 + mt * 16 + g;
#pragma unroll
        for (int nt = 0; nt < 4; nt++) {
            int c = wn * 32 + nt * 8 + tg * 2;
            *(__half2*)&S.sc[r0][c]     = __floats2half2_rn(acc[mt][nt][0], acc[mt][nt][1]);
            *(__half2*)&S.sc[r0 + 8][c] = __floats2half2_rn(acc[mt][nt][2], acc[mt][nt][3]);
        }
    }
    __syncthreads();

    // ---- ctx partial via fp16 MMA: per warp M=32(d) x N=32(e) x K=32(p)
    {
        const int h  = warp >> 2, hb = h * 32;
        const int pb0 = (warp & 3) * 32;
        float cacc[2][4][4] = {};
#pragma unroll
        for (int ks = 0; ks < 2; ks++) {
            const int pw = pb0 + ks * 16;
            unsigned af[2][4], bf[4][2];
#pragma unroll
            for (int mt = 0; mt < 2; mt++) {
                int dm = hb + mt * 16 + g;
                af[mt][0] = *(const unsigned*)&S.sc[dm][pw + 2 * tg];
                af[mt][1] = *(const unsigned*)&S.sc[dm + 8][pw + 2 * tg];
                af[mt][2] = *(const unsigned*)&S.sc[dm][pw + 2 * tg + 8];
                af[mt][3] = *(const unsigned*)&S.sc[dm + 8][pw + 2 * tg + 8];
            }
#pragma unroll
            for (int nt = 0; nt < 4; nt++) {
                int en = 64 + hb + nt * 8 + g;
                bf[nt][0] = *(const unsigned*)&S.sc[en][pw + 2 * tg];
                bf[nt][1] = *(const unsigned*)&S.sc[en][pw + 2 * tg + 8];
            }
#pragma unroll
            for (int mt = 0; mt < 2; mt++)
#pragma unroll
                for (int nt = 0; nt < 4; nt++)
                    mma_f16(cacc[mt][nt], af[mt], bf[nt]);
        }
#pragma unroll
        for (int mt = 0; mt < 2; mt++) {
            int d = mt * 16 + g;
#pragma unroll
            for (int nt = 0; nt < 4; nt++) {
                int e = nt * 8 + tg * 2;
                S.u.P[warp][d][e]         = cacc[mt][nt][0];
                S.u.P[warp][d][e + 1]     = cacc[mt][nt][1];
                S.u.P[warp][d + 8][e]     = cacc[mt][nt][2];
                S.u.P[warp][d + 8][e + 1] = cacc[mt][nt][3];
            }
        }
    }
    __syncthreads();

    // ---- reduce 4 K-slices per head, write ctx partial
    {
        float* op = g_ctxp + (((size_t)(b * HEADS_ + hp * 2)) * 32 + pt) * (D_ * D_);
#pragma unroll
        for (int i = 0; i < 8; i++) {
            int elem = tid + i * 256;
            int hh = elem >> 10;
            int de = elem & 1023;
            int d = de >> 5, e = de & 31;
            float s = S.u.P[hh * 4 + 0][d][e] + S.u.P[hh * 4 + 1][d][e]
                    + S.u.P[hh * 4 + 2][d][e] + S.u.P[hh * 4 + 3][d][e];
            op[(size_t)hh * 32 * (D_ * D_) + de] = s;
        }
    }
}

// =====================================================================
// Kernel 2: reduce ctx partials + w_eff = w_out(head slice) @ ctx -> fp16
// =====================================================================
__global__ void __launch_bounds__(256) k_weff(const float* __restrict__ w_out) {
    const int h = blockIdx.x, b = blockIdx.y;
    const int bh = b * HEADS_ + h;
    const int t = threadIdx.x;

    __shared__ float ctxs[32][33];
    __shared__ float ws[256][33];

    const float* pp = g_ctxp + (size_t)bh * 32 * (D_ * D_);
#pragma unroll
    for (int i = 0; i < 4; i++) {
        int elem = t + i * 256;
        float s = 0.f;
#pragma unroll
        for (int pg = 0; pg < 32; pg++) s += pp[pg * (D_ * D_) + elem];
        ctxs[elem >> 5][elem & 31] = s;
    }
#pragma unroll
    for (int i = 0; i < 32; i++) {
        int idx = t + i * 256;
        int r = idx >> 5, c = idx & 31;
        ws[r][c] = w_out[(size_t)r * C_ + h * D_ + c];
    }
    __syncthreads();

    float we[32] = {};
#pragma unroll
    for (int d = 0; d < 32; d++) {
        float wv = ws[t][d];
#pragma unroll
        for (int e = 0; e < 32; e++) we[e] += wv * ctxs[d][e];
    }
    __half* op = g_weffh + ((size_t)b * C_ + t) * C_ + h * D_;
#pragma unroll
    for (int e2 = 0; e2 < 16; e2++)
        *(__half2*)&op[e2 * 2] = __floats2half2_rn(we[e2 * 2], we[e2 * 2 + 1]);
}

// =====================================================================
// Kernel 3: out = w_eff[b] @ qhat + b_out, fused channel LayerNorm (fp16 MMA)
// block 256(M) x 64(N) x 256(K); 8 warps (4x2).
// =====================================================================
__global__ void __launch_bounds__(256) k_out_ln(const float* __restrict__ b_out,
                                                const float* __restrict__ gamma,
                                                const float* __restrict__ beta,
                                                float* __restrict__ out) {
    extern __shared__ char smem_raw[];
    OutSmem& S = *reinterpret_cast<OutSmem*>(smem_raw);

    const int tid  = threadIdx.x;
    const int warp = tid >> 5, lane = tid & 31;
    const int g = lane >> 2, tg = lane & 3;
    const int wm = warp >> 1, wn = warp & 1;

    const int blk = blockIdx.x;
    const int b   = blk >> 6;
    const int p0  = (blk & 63) * 64;

    if (tid < 64) { S.s_sum[tid] = 0.f; S.s_sq[tid] = 0.f; }

    // hoisted pointers: A = g_weffh rows; B = g_q2 [c2][pixel]
    const __half* pa[4]; const __half2* pb;
    unsigned sa[2][4], sb[2];
#pragma unroll
    for (int i = 0; i < 4; i++) {
        int f4 = tid + i * 256;
        int ra = f4 >> 2, ca = (f4 & 3) * 8;        // 256 rows x 32 halves
        pa[i] = g_weffh + (size_t)b * C_ * C_ + (size_t)ra * C_ + ca;
        sa[0][i] = s2u(&S.As[0][ra][ca]);
        sa[1][i] = s2u(&S.As[1][ra][ca]);
    }
    {
        int rb = tid >> 4, cb = (tid & 15) * 4;     // 16 c2-rows x 64 half2
        pb = g_q2 + ((size_t)b * 128 + rb) * HW_ + p0 + cb;
        sb[0] = s2u(&S.Bs[0][rb][cb]);
        sb[1] = s2u(&S.Bs[1][rb][cb]);
    }

    float acc[4][4][4] = {};

#pragma unroll
    for (int i = 0; i < 4; i++) { cp16s(sa[0][i], pa[i]); pa[i] += 32; }
    cp16s(sb[0], pb); pb += 16 * HW_;
    CP_COMMIT();

    int buf = 0;
    for (int it = 0; it < 8; it++) {
        if (it < 7) {
#pragma unroll
            for (int i = 0; i < 4; i++) { cp16s(sa[buf ^ 1][i], pa[i]); pa[i] += 32; }
            cp16s(sb[buf ^ 1], pb); pb += 16 * HW_;
            CP_COMMIT();
            CP_WAIT(1);
        } else {
            CP_WAIT(0);
        }
        __syncthreads();

#pragma unroll
        for (int ks = 0; ks < 2; ks++) {
            const int kA = ks * 16;
            unsigned af[4][4], bf[4][2];
#pragma unroll
            for (int mt = 0; mt < 4; mt++) {
                int rm = wm * 64 + mt * 16;
                af[mt][0] = *(const unsigned*)&S.As[buf][rm + g][kA + 2 * tg];
                af[mt][1] = *(const unsigned*)&S.As[buf][rm + g + 8][kA + 2 * tg];
                af[mt][2] = *(const unsigned*)&S.As[buf][rm + g][kA + 2 * tg + 8];
                af[mt][3] = *(const unsigned*)&S.As[buf][rm + g + 8][kA + 2 * tg + 8];
            }
#pragma unroll
            for (int nt = 0; nt < 4; nt++) {
                int cn = wn * 32 + nt * 8 + g;
                bf[nt][0] = h2u(S.Bs[buf][ks * 8 + tg][cn]);
                bf[nt][1] = h2u(S.Bs[buf][ks * 8 + tg + 4][cn]);
            }
#pragma unroll
            for (int mt = 0; mt < 4; mt++)
#pragma unroll
                for (int nt = 0; nt < 4; nt++)
                    mma_f16(acc[mt][nt], af[mt], bf[nt]);
        }
        __syncthreads();
        buf ^= 1;
    }

    float bias0[4], bias1[4], gam0[4], gam1[4], bet0[4], bet1[4];
#pragma unroll
    for (int mt = 0; mt < 4; mt++) {
        int r = wm * 64 + mt * 16 + g;
        bias0[mt] = b_out[r]; bias1[mt] = b_out[r + 8];
        gam0[mt]  = gamma[r]; gam1[mt]  = gamma[r + 8];
        bet0[mt]  = beta[r];  bet1[mt]  = beta[r + 8];
    }
#pragma unroll
    for (int mt = 0; mt < 4; mt++)
#pragma unroll
        for (int nt = 0; nt < 4; nt++) {
            acc[mt][nt][0] += bias0[mt]; acc[mt][nt][1] += bias0[mt];
            acc[mt][nt][2] += bias1[mt]; acc[mt][nt][3] += bias1[mt];
        }

#pragma unroll
    for (int nt = 0; nt < 4; nt++) {
        float s0 = 0.f, s1 = 0.f, q0 = 0.f, q1 = 0.f;
#pragma unroll
        for (int mt = 0; mt < 4; mt++) {
            float v0 = acc[mt][nt][0], v1 = acc[mt][nt][1];
            float v2 = acc[mt][nt][2], v3 = acc[mt][nt][3];
            s0 += v0 + v2; s1 += v1 + v3;
            q0 += v0 * v0 + v2 * v2; q1 += v1 * v1 + v3 * v3;
        }
#pragma unroll
        for (int off = 4; off < 32; off <<= 1) {
            s0 += __shfl_xor_sync(0xffffffffu, s0, off);
            s1 += __shfl_xor_sync(0xffffffffu, s1, off);
            q0 += __shfl_xor_sync(0xffffffffu, q0, off);
            q1 += __shfl_xor_sync(0xffffffffu, q1, off);
        }
        if (g == 0) {
            int c = wn * 32 + nt * 8 + tg * 2;
            atomicAdd(&S.s_sum[c], s0);     atomicAdd(&S.s_sq[c], q0);
            atomicAdd(&S.s_sum[c + 1], s1); atomicAdd(&S.s_sq[c + 1], q1);
        }
    }
    __syncthreads();

    if (tid < 64) {
        float mu  = S.s_sum[tid] * (1.0f / 256.0f);
        float var = S.s_sq[tid] * (1.0f / 256.0f) - mu * mu;
        S.s_mu[tid] = mu;
        S.s_rs[tid] = rsqrtf(var + LN_EPS);
    }
    __syncthreads();

    float* ob = out + (size_t)b * (C_ * HW_) + p0;
#pragma unroll
    for (int mt = 0; mt < 4; mt++) {
        int r = wm * 64 + mt * 16 + g;
#pragma unroll
        for (int nt = 0; nt < 4; nt++) {
            int c = wn * 32 + nt * 8 + tg * 2;
            float mu0 = S.s_mu[c], rs0 = S.s_rs[c];
            float mu1 = S.s_mu[c + 1], rs1 = S.s_rs[c + 1];
            float o0 = (acc[mt][nt][0] - mu0) * rs0 * gam0[mt] + bet0[mt];
            float o1 = (acc[mt][nt][1] - mu1) * rs1 * gam0[mt] + bet0[mt];
            float o2 = (acc[mt][nt][2] - mu0) * rs0 * gam1[mt] + bet1[mt];
            float o3 = (acc[mt][nt][3] - mu1) * rs1 * gam1[mt] + bet1[mt];
            *(float2*)&ob[(size_t)r * HW_ + c]       = make_float2(o0, o1);
            *(float2*)&ob[(size_t)(r + 8) * HW_ + c] = make_float2(o2, o3);
        }
    }
}

// =====================================================================
extern "C" void kernel_launch(void* const* d_in, const int* in_sizes, int n_in,
                              void* d_out, int out_size) {
    const float* x      = (const float*)d_in[0];
    const float* w_qkv  = (const float*)d_in[1];
    const float* w_out  = (const float*)d_in[2];
    const float* b_out  = (const float*)d_in[3];
    const float* gamma  = (const float*)d_in[4];
    const float* beta   = (const float*)d_in[5];
    float* out = (float*)d_out;

    cudaFuncSetAttribute(k_main, cudaFuncAttributeMaxDynamicSharedMemorySize,
                         (int)sizeof(MainSmem));
    cudaFuncSetAttribute(k_out_ln, cudaFuncAttributeMaxDynamicSharedMemorySize,
                         (int)sizeof(OutSmem));

    k_prex<<<(B_ * 128 * 1024) / 256, 256>>>(x);          // 8192 blocks
    k_prew<<<(3 * C_ * C_) / 4 / 256, 256>>>(w_qkv);      // 192 blocks

    k_main<<<1024 + 2048, 256, sizeof(MainSmem)>>>();     // q blocks, then kv

    dim3 g3(HEADS_, B_);                                  // 8 x 16
    k_weff<<<g3, 256>>>(w_out);

    k_out_ln<<<(B_ * HW_) / 64, 256, sizeof(OutSmem)>>>(b_out, gamma, beta, out);
}

// round 11
// speedup vs baseline: 1.7808x; 1.2191x over previous
#include <cuda_runtime.h>
#include <cuda_fp16.h>

// ---------------- problem constants ----------------
#define B_      16
#define C_      256
#define HEADS_  8
#define D_      32          // dim_head
#define HW_     4096        // 64*64
#define W_      64
#define LN_EPS  1e-5f

// ---------------- scratch (no allocations allowed) ----------------
__device__ __half  g_wqh[3 * C_ * C_];                    // w_qkv fp16
__device__ __half2 g_xh[(size_t)B_ * 128 * HW_];          // x packed [b][c2][p]
__device__ __half2 g_q2[(size_t)B_ * 128 * HW_];          // qhat packed [b][c2][p]
__device__ float   g_ctxp[(size_t)B_ * HEADS_ * 32 * (D_ * D_)];
__device__ __half  g_weffh[(size_t)B_ * C_ * C_];         // w_eff fp16

// ---------------- helpers ----------------
__device__ __forceinline__ unsigned h2u(__half2 h) { return *(unsigned*)&h; }

__device__ __forceinline__ void mma_f16(float* c, const unsigned* a, const unsigned* b) {
    asm volatile(
        "mma.sync.aligned.m16n8k16.row.col.f32.f16.f16.f32 "
        "{%0,%1,%2,%3}, {%4,%5,%6,%7}, {%8,%9}, {%0,%1,%2,%3};"
        : "+f"(c[0]), "+f"(c[1]), "+f"(c[2]), "+f"(c[3])
        : "r"(a[0]), "r"(a[1]), "r"(a[2]), "r"(a[3]), "r"(b[0]), "r"(b[1]));
}

__device__ __forceinline__ void ldsm_x4(unsigned* r, unsigned saddr) {
    asm volatile("ldmatrix.sync.aligned.m8n8.x4.shared.b16 {%0,%1,%2,%3}, [%4];"
        : "=r"(r[0]), "=r"(r[1]), "=r"(r[2]), "=r"(r[3]) : "r"(saddr));
}

__device__ __forceinline__ unsigned s2u(const void* p) {
    return (unsigned)__cvta_generic_to_shared(p);
}
__device__ __forceinline__ void cp16s(unsigned sdst, const void* gsrc) {
    asm volatile("cp.async.cg.shared.global [%0], [%1], 16;" :: "r"(sdst), "l"(gsrc));
}
#define CP_COMMIT()  asm volatile("cp.async.commit_group;")
#define CP_WAIT(n)   asm volatile("cp.async.wait_group %0;" :: "n"(n))

// ---------------- dynamic smem layouts ----------------
#define A_STRIDE_B  80    // 40 halves per row
struct MainSmem {
    union {
        struct {
            __half  As[2][128][40];    // [m][k] halves; LDSM rows phase-conflict-free
            __half2 Bs[2][16][136];    // [k2][pixel] chan-pairs, pad 136 -> 8tg+g
        } ld;
        float P[8][32][33];            // per-warp ctx partials (dead-As/Bs overlay)
    } u;
    __half sc[128][136];               // [row][pixel] khat|v halves
    float red[2][4][64];               // k-softmax cross-warp partials
};
struct OutSmem {
    __half  As[2][256][40];
    __half2 Bs[2][16][72];             // pad 72 -> 8tg+g bijective
    float s_sum[64], s_sq[64], s_mu[64], s_rs[64];
};

// =====================================================================
// Kernel 0a: pack x -> fp16 [b][c2][p] half2 (chan 2c2, 2c2+1 per pixel)
// =====================================================================
__global__ void __launch_bounds__(256) k_prex(const float* __restrict__ x) {
    unsigned i = blockIdx.x * 256 + threadIdx.x;     // (b, c2, p4)
    int p4 = i & 1023;
    int c2 = (i >> 10) & 127;
    int b  = i >> 17;
    const float4 v0 = *(const float4*)&x[((size_t)b * C_ + 2 * c2)     * HW_ + p4 * 4];
    const float4 v1 = *(const float4*)&x[((size_t)b * C_ + 2 * c2 + 1) * HW_ + p4 * 4];
    __half2* dst = &g_xh[((size_t)b * 128 + c2) * HW_ + p4 * 4];
    dst[0] = __floats2half2_rn(v0.x, v1.x);
    dst[1] = __floats2half2_rn(v0.y, v1.y);
    dst[2] = __floats2half2_rn(v0.z, v1.z);
    dst[3] = __floats2half2_rn(v0.w, v1.w);
}

// Kernel 0b: w_qkv -> fp16 (row-major, natural K-pairing for A operand)
__global__ void __launch_bounds__(256) k_prew(const float* __restrict__ w) {
    unsigned i = blockIdx.x * 256 + threadIdx.x;
    float4 v = ((const float4*)w)[i];
    __half2* dst = (__half2*)&g_wqh[(size_t)i * 4];
    dst[0] = __floats2half2_rn(v.x, v.y);
    dst[1] = __floats2half2_rn(v.z, v.w);
}

// =====================================================================
// Kernel 1 (MERGED): bid < 1024 -> q path; bid >= 1024 -> kv+ctx path.
// fp16 m16n8k16, 128x128x256 tiles, 8 warps (2x4), fp32 accumulate.
// A fragments via ldmatrix.x4.
// =====================================================================
__global__ void __launch_bounds__(256) k_main() {
    extern __shared__ char smem_raw[];
    MainSmem& S = *reinterpret_cast<MainSmem*>(smem_raw);

    const int tid  = threadIdx.x;
    const int warp = tid >> 5, lane = tid & 31;
    const int g = lane >> 2, tg = lane & 3;
    const int wm = warp >> 2, wn = warp & 3;

    const int bid = blockIdx.x;
    const bool isQ = bid < 1024;
    int m0 = 0, b, p0, hp = 0, pt = 0;
    if (isQ) {
        m0 = (bid >> 9) * 128;
        int t = bid & 511;
        b  = t >> 5;
        p0 = (t & 31) * 128;
    } else {
        int k2 = bid - 1024;
        hp = k2 & 3;
        pt = (k2 >> 2) & 31;
        b  = k2 >> 7;
        p0 = pt * 128;
    }

    // hoisted pointers: A (w rows, halves), B (g_xh half2)
    const __half* pa[2]; const __half2* pb[2];
    unsigned sa[2][2], sb[2][2];
#pragma unroll
    for (int i = 0; i < 2; i++) {
        int f4 = tid + i * 256;
        int ra = f4 >> 2, ca = (f4 & 3) * 8;         // 128 rows x 32 halves
        int gr = isQ ? (m0 + ra)
                     : ((ra < 64) ? (C_ + hp * 64 + ra) : (2 * C_ + hp * 64 + ra - 64));
        pa[i] = g_wqh + (size_t)gr * C_ + ca;
        sa[0][i] = s2u(&S.u.ld.As[0][ra][ca]);
        sa[1][i] = s2u(&S.u.ld.As[1][ra][ca]);
        int rb = f4 >> 5, cb = (f4 & 31) * 4;        // 16 c2-rows x 128 half2
        pb[i] = g_xh + ((size_t)b * 128 + rb) * HW_ + p0 + cb;
        sb[0][i] = s2u(&S.u.ld.Bs[0][rb][cb]);
        sb[1][i] = s2u(&S.u.ld.Bs[1][rb][cb]);
    }

    // ldmatrix per-lane base addresses (rows lane&15, col-half (lane>>4)*8)
    const int lmRow = wm * 64 + (lane & 15);
    const int lmCol = (lane >> 4) * 8;
    unsigned baseA[2];
    baseA[0] = s2u(&S.u.ld.As[0][lmRow][lmCol]);
    baseA[1] = s2u(&S.u.ld.As[1][lmRow][lmCol]);

    float acc[4][4][4] = {};

#pragma unroll
    for (int i = 0; i < 2; i++) {
        cp16s(sa[0][i], pa[i]);  pa[i] += 32;
        cp16s(sb[0][i], pb[i]);  pb[i] += 16 * HW_;
    }
    CP_COMMIT();

    int buf = 0;
    for (int it = 0; it < 8; it++) {
        if (it < 7) {
#pragma unroll
            for (int i = 0; i < 2; i++) {
                cp16s(sa[buf ^ 1][i], pa[i]);  pa[i] += 32;
                cp16s(sb[buf ^ 1][i], pb[i]);  pb[i] += 16 * HW_;
            }
            CP_COMMIT();
            CP_WAIT(1);
        } else {
            CP_WAIT(0);
        }
        __syncthreads();
#pragma unroll
        for (int ks = 0; ks < 2; ks++) {
            unsigned af[4][4], bf[4][2];
#pragma unroll
            for (int mt = 0; mt < 4; mt++)
                ldsm_x4(af[mt], baseA[buf] + mt * (16 * A_STRIDE_B) + ks * 32);
#pragma unroll
            for (int nt = 0; nt < 4; nt++) {
                int cn = wn * 32 + nt * 8 + g;
                bf[nt][0] = h2u(S.u.ld.Bs[buf][ks * 8 + tg][cn]);
                bf[nt][1] = h2u(S.u.ld.Bs[buf][ks * 8 + tg + 4][cn]);
            }
#pragma unroll
            for (int mt = 0; mt < 4; mt++)
#pragma unroll
                for (int nt = 0; nt < 4; nt++)
                    mma_f16(acc[mt][nt], af[mt], bf[nt]);
        }
        __syncthreads();
        buf ^= 1;
    }

    if (isQ) {
        // ---- q-softmax over d=32 (head = mt-pair; rows span g via shfl)
#pragma unroll
        for (int p = 0; p < 2; p++) {
#pragma unroll
            for (int nt = 0; nt < 4; nt++) {
#pragma unroll
                for (int j = 0; j < 2; j++) {
                    float v0 = acc[2 * p][nt][j],     v1 = acc[2 * p][nt][j + 2];
                    float v2 = acc[2 * p + 1][nt][j], v3 = acc[2 * p + 1][nt][j + 2];
                    float m = fmaxf(fmaxf(v0, v1), fmaxf(v2, v3));
                    m = fmaxf(m, __shfl_xor_sync(0xffffffffu, m, 4));
                    m = fmaxf(m, __shfl_xor_sync(0xffffffffu, m, 8));
                    m = fmaxf(m, __shfl_xor_sync(0xffffffffu, m, 16));
                    float e0 = __expf(v0 - m), e1 = __expf(v1 - m);
                    float e2 = __expf(v2 - m), e3 = __expf(v3 - m);
                    float s = e0 + e1 + e2 + e3;
                    s += __shfl_xor_sync(0xffffffffu, s, 4);
                    s += __shfl_xor_sync(0xffffffffu, s, 8);
                    s += __shfl_xor_sync(0xffffffffu, s, 16);
                    float inv = 1.0f / s;
                    acc[2 * p][nt][j]         = e0 * inv;
                    acc[2 * p][nt][j + 2]     = e1 * inv;
                    acc[2 * p + 1][nt][j]     = e2 * inv;
                    acc[2 * p + 1][nt][j + 2] = e3 * inv;
                }
            }
        }
        // ---- paired fp16 store: channel pairs (r0, r0+1) via shfl_xor(4)
#pragma unroll
        for (int mt = 0; mt < 4; mt++) {
            int r0 = m0 + wm * 64 + mt * 16 + g;
#pragma unroll
            for (int nt = 0; nt < 4; nt++) {
                float o0 = acc[mt][nt][0], o1 = acc[mt][nt][1];
                float o2 = acc[mt][nt][2], o3 = acc[mt][nt][3];
                float q0 = __shfl_xor_sync(0xffffffffu, o0, 4);
                float q1 = __shfl_xor_sync(0xffffffffu, o1, 4);
                float q2 = __shfl_xor_sync(0xffffffffu, o2, 4);
                float q3 = __shfl_xor_sync(0xffffffffu, o3, 4);
                if (!(g & 1)) {
                    int c = wn * 32 + nt * 8 + tg * 2;
                    __half2* d0 = &g_q2[((size_t)b * 128 + (r0 >> 1)) * HW_ + p0 + c];
                    d0[0] = __floats2half2_rn(o0, q0);
                    d0[1] = __floats2half2_rn(o1, q1);
                    __half2* d1 = d0 + (size_t)4 * HW_;     // rows r0+8, r0+9
                    d1[0] = __floats2half2_rn(o2, q2);
                    d1[1] = __floats2half2_rn(o3, q3);
                }
            }
        }
        return;
    }

    // ================= kv path =================
    // ---- k-softmax over y=64 (rows 0-63 -> wm==0 warps)
    float mloc[4][2], sloc[4][2];
    if (wm == 0) {
#pragma unroll
        for (int mt = 0; mt < 4; mt++)
#pragma unroll
            for (int hf = 0; hf < 2; hf++) {
                float m = -1e30f;
#pragma unroll
                for (int nt = 0; nt < 4; nt++) {
                    m = fmaxf(m, acc[mt][nt][hf * 2]);
                    m = fmaxf(m, acc[mt][nt][hf * 2 + 1]);
                }
                m = fmaxf(m, __shfl_xor_sync(0xffffffffu, m, 1));
                m = fmaxf(m, __shfl_xor_sync(0xffffffffu, m, 2));
                mloc[mt][hf] = m;
                if (tg == 0) S.red[0][wn][mt * 16 + hf * 8 + g] = m;
            }
    }
    __syncthreads();
    if (wm == 0) {
#pragma unroll
        for (int mt = 0; mt < 4; mt++)
#pragma unroll
            for (int hf = 0; hf < 2; hf++) {
                int ri = mt * 16 + hf * 8 + g;
                float m = fmaxf(mloc[mt][hf], S.red[0][wn ^ 1][ri]);
                float s = 0.f;
#pragma unroll
                for (int nt = 0; nt < 4; nt++) {
                    float e0 = __expf(acc[mt][nt][hf * 2] - m);
                    float e1 = __expf(acc[mt][nt][hf * 2 + 1] - m);
                    acc[mt][nt][hf * 2]     = e0;
                    acc[mt][nt][hf * 2 + 1] = e1;
                    s += e0 + e1;
                }
                s += __shfl_xor_sync(0xffffffffu, s, 1);
                s += __shfl_xor_sync(0xffffffffu, s, 2);
                sloc[mt][hf] = s;
                if (tg == 0) S.red[1][wn][ri] = s;
            }
    }
    __syncthreads();
    if (wm == 0) {
#pragma unroll
        for (int mt = 0; mt < 4; mt++)
#pragma unroll
            for (int hf = 0; hf < 2; hf++) {
                int ri = mt * 16 + hf * 8 + g;
                float inv = 1.0f / (sloc[mt][hf] + S.red[1][wn ^ 1][ri]);
#pragma unroll
                for (int nt = 0; nt < 4; nt++) {
                    acc[mt][nt][hf * 2]     *= inv;
                    acc[mt][nt][hf * 2 + 1] *= inv;
                }
            }
    }
    __syncthreads();

    // ---- store sc[row][pixel] as fp16 (half2 per pixel pair)
#pragma unroll
    for (int mt = 0; mt < 4; mt++) {
        int r0 = wm * 64 + mt * 16 + g;
#pragma unroll
        for (int nt = 0; nt < 4; nt++) {
            int c = wn * 32 + nt * 8 + tg * 2;
            *(__half2*)&S.sc[r0][c]     = __floats2half2_rn(acc[mt][nt][0], acc[mt][nt][1]);
            *(__half2*)&S.sc[r0 + 8][c] = __floats2half2_rn(acc[mt][nt][2], acc[mt][nt][3]);
        }
    }
    __syncthreads();

    // ---- ctx partial via fp16 MMA: per warp M=32(d) x N=32(e) x K=32(p)
    {
        const int h  = warp >> 2, hb = h * 32;
        const int pb0 = (warp & 3) * 32;
        float cacc[2][4][4] = {};
#pragma unroll
        for (int ks = 0; ks < 2; ks++) {
            const int pw = pb0 + ks * 16;
            unsigned af[2][4], bf[4][2];
#pragma unroll
            for (int mt = 0; mt < 2; mt++) {
                int dm = hb + mt * 16 + g;
                af[mt][0] = *(const unsigned*)&S.sc[dm][pw + 2 * tg];
                af[mt][1] = *(const unsigned*)&S.sc[dm + 8][pw + 2 * tg];
                af[mt][2] = *(const unsigned*)&S.sc[dm][pw + 2 * tg + 8];
                af[mt][3] = *(const unsigned*)&S.sc[dm + 8][pw + 2 * tg + 8];
            }
#pragma unroll
            for (int nt = 0; nt < 4; nt++) {
                int en = 64 + hb + nt * 8 + g;
                bf[nt][0] = *(const unsigned*)&S.sc[en][pw + 2 * tg];
                bf[nt][1] = *(const unsigned*)&S.sc[en][pw + 2 * tg + 8];
            }
#pragma unroll
            for (int mt = 0; mt < 2; mt++)
#pragma unroll
                for (int nt = 0; nt < 4; nt++)
                    mma_f16(cacc[mt][nt], af[mt], bf[nt]);
        }
#pragma unroll
        for (int mt = 0; mt < 2; mt++) {
            int d = mt * 16 + g;
#pragma unroll
            for (int nt = 0; nt < 4; nt++) {
                int e = nt * 8 + tg * 2;
                S.u.P[warp][d][e]         = cacc[mt][nt][0];
                S.u.P[warp][d][e + 1]     = cacc[mt][nt][1];
                S.u.P[warp][d + 8][e]     = cacc[mt][nt][2];
                S.u.P[warp][d + 8][e + 1] = cacc[mt][nt][3];
            }
        }
    }
    __syncthreads();

    // ---- reduce 4 K-slices per head, write ctx partial
    {
        float* op = g_ctxp + (((size_t)(b * HEADS_ + hp * 2)) * 32 + pt) * (D_ * D_);
#pragma unroll
        for (int i = 0; i < 8; i++) {
            int elem = tid + i * 256;
            int hh = elem >> 10;
            int de = elem & 1023;
            int d = de >> 5, e = de & 31;
            float s = S.u.P[hh * 4 + 0][d][e] + S.u.P[hh * 4 + 1][d][e]
                    + S.u.P[hh * 4 + 2][d][e] + S.u.P[hh * 4 + 3][d][e];
            op[(size_t)hh * 32 * (D_ * D_) + de] = s;
        }
    }
}

// =====================================================================
// Kernel 2: reduce ctx partials (float4, ILP) + w_eff = w_out @ ctx -> fp16
// =====================================================================
__global__ void __launch_bounds__(256) k_weff(const float* __restrict__ w_out) {
    const int h = blockIdx.x, b = blockIdx.y;
    const int bh = b * HEADS_ + h;
    const int t = threadIdx.x;

    __shared__ float ctxs[32][36];    // pad 36: float4-aligned rows
    __shared__ float ws[256][33];

    // vectorized 32-partial reduction: thread t owns elems 4t..4t+3
    {
        const float4* pp4 = (const float4*)(g_ctxp + (size_t)bh * 32 * (D_ * D_));
        float4 s0 = make_float4(0.f, 0.f, 0.f, 0.f);
        float4 s1 = s0, s2 = s0, s3 = s0;
#pragma unroll
        for (int pg = 0; pg < 32; pg += 4) {
            float4 v0 = pp4[(pg + 0) * 256 + t];
            float4 v1 = pp4[(pg + 1) * 256 + t];
            float4 v2 = pp4[(pg + 2) * 256 + t];
            float4 v3 = pp4[(pg + 3) * 256 + t];
            s0.x += v0.x; s0.y += v0.y; s0.z += v0.z; s0.w += v0.w;
            s1.x += v1.x; s1.y += v1.y; s1.z += v1.z; s1.w += v1.w;
            s2.x += v2.x; s2.y += v2.y; s2.z += v2.z; s2.w += v2.w;
            s3.x += v3.x; s3.y += v3.y; s3.z += v3.z; s3.w += v3.w;
        }
        float4 s = make_float4(s0.x + s1.x + s2.x + s3.x, s0.y + s1.y + s2.y + s3.y,
                               s0.z + s1.z + s2.z + s3.z, s0.w + s1.w + s2.w + s3.w);
        *(float4*)&ctxs[t >> 3][(t & 7) * 4] = s;
    }
#pragma unroll
    for (int i = 0; i < 32; i++) {
        int idx = t + i * 256;
        int r = idx >> 5, c = idx & 31;
        ws[r][c] = w_out[(size_t)r * C_ + h * D_ + c];
    }
    __syncthreads();

    float we[32] = {};
#pragma unroll
    for (int d = 0; d < 32; d++) {
        float wv = ws[t][d];
#pragma unroll
        for (int e = 0; e < 32; e++) we[e] += wv * ctxs[d][e];
    }
    __half* op = g_weffh + ((size_t)b * C_ + t) * C_ + h * D_;
#pragma unroll
    for (int e2 = 0; e2 < 16; e2++)
        *(__half2*)&op[e2 * 2] = __floats2half2_rn(we[e2 * 2], we[e2 * 2 + 1]);
}

// =====================================================================
// Kernel 3: out = w_eff[b] @ qhat + b_out, fused channel LayerNorm (fp16 MMA)
// block 256(M) x 64(N) x 256(K); 8 warps (4x2); A via ldmatrix.x4.
// =====================================================================
__global__ void __launch_bounds__(256) k_out_ln(const float* __restrict__ b_out,
                                                const float* __restrict__ gamma,
                                                const float* __restrict__ beta,
                                                float* __restrict__ out) {
    extern __shared__ char smem_raw[];
    OutSmem& S = *reinterpret_cast<OutSmem*>(smem_raw);

    const int tid  = threadIdx.x;
    const int warp = tid >> 5, lane = tid & 31;
    const int g = lane >> 2, tg = lane & 3;
    const int wm = warp >> 1, wn = warp & 1;

    const int blk = blockIdx.x;
    const int b   = blk >> 6;
    const int p0  = (blk & 63) * 64;

    if (tid < 64) { S.s_sum[tid] = 0.f; S.s_sq[tid] = 0.f; }

    // hoisted pointers: A = g_weffh rows; B = g_q2 [c2][pixel]
    const __half* pa[4]; const __half2* pb;
    unsigned sa[2][4], sb[2];
#pragma unroll
    for (int i = 0; i < 4; i++) {
        int f4 = tid + i * 256;
        int ra = f4 >> 2, ca = (f4 & 3) * 8;        // 256 rows x 32 halves
        pa[i] = g_weffh + (size_t)b * C_ * C_ + (size_t)ra * C_ + ca;
        sa[0][i] = s2u(&S.As[0][ra][ca]);
        sa[1][i] = s2u(&S.As[1][ra][ca]);
    }
    {
        int rb = tid >> 4, cb = (tid & 15) * 4;     // 16 c2-rows x 64 half2
        pb = g_q2 + ((size_t)b * 128 + rb) * HW_ + p0 + cb;
        sb[0] = s2u(&S.Bs[0][rb][cb]);
        sb[1] = s2u(&S.Bs[1][rb][cb]);
    }

    // ldmatrix per-lane base addresses
    const int lmRow = wm * 64 + (lane & 15);
    const int lmCol = (lane >> 4) * 8;
    unsigned baseA[2];
    baseA[0] = s2u(&S.As[0][lmRow][lmCol]);
    baseA[1] = s2u(&S.As[1][lmRow][lmCol]);

    float acc[4][4][4] = {};

#pragma unroll
    for (int i = 0; i < 4; i++) { cp16s(sa[0][i], pa[i]); pa[i] += 32; }
    cp16s(sb[0], pb); pb += 16 * HW_;
    CP_COMMIT();

    int buf = 0;
    for (int it = 0; it < 8; it++) {
        if (it < 7) {
#pragma unroll
            for (int i = 0; i < 4; i++) { cp16s(sa[buf ^ 1][i], pa[i]); pa[i] += 32; }
            cp16s(sb[buf ^ 1], pb); pb += 16 * HW_;
            CP_COMMIT();
            CP_WAIT(1);
        } else {
            CP_WAIT(0);
        }
        __syncthreads();

#pragma unroll
        for (int ks = 0; ks < 2; ks++) {
            unsigned af[4][4], bf[4][2];
#pragma unroll
            for (int mt = 0; mt < 4; mt++)
                ldsm_x4(af[mt], baseA[buf] + mt * (16 * A_STRIDE_B) + ks * 32);
#pragma unroll
            for (int nt = 0; nt < 4; nt++) {
                int cn = wn * 32 + nt * 8 + g;
                bf[nt][0] = h2u(S.Bs[buf][ks * 8 + tg][cn]);
                bf[nt][1] = h2u(S.Bs[buf][ks * 8 + tg + 4][cn]);
            }
#pragma unroll
            for (int mt = 0; mt < 4; mt++)
#pragma unroll
                for (int nt = 0; nt < 4; nt++)
                    mma_f16(acc[mt][nt], af[mt], bf[nt]);
        }
        __syncthreads();
        buf ^= 1;
    }

    float bias0[4], bias1[4], gam0[4], gam1[4], bet0[4], bet1[4];
#pragma unroll
    for (int mt = 0; mt < 4; mt++) {
        int r = wm * 64 + mt * 16 + g;
        bias0[mt] = b_out[r]; bias1[mt] = b_out[r + 8];
        gam0[mt]  = gamma[r]; gam1[mt]  = gamma[r + 8];
        bet0[mt]  = beta[r];  bet1[mt]  = beta[r + 8];
    }
#pragma unroll
    for (int mt = 0; mt < 4; mt++)
#pragma unroll
        for (int nt = 0; nt < 4; nt++) {
            acc[mt][nt][0] += bias0[mt]; acc[mt][nt][1] += bias0[mt];
            acc[mt][nt][2] += bias1[mt]; acc[mt][nt][3] += bias1[mt];
        }

#pragma unroll
    for (int nt = 0; nt < 4; nt++) {
        float s0 = 0.f, s1 = 0.f, q0 = 0.f, q1 = 0.f;
#pragma unroll
        for (int mt = 0; mt < 4; mt++) {
            float v0 = acc[mt][nt][0], v1 = acc[mt][nt][1];
            float v2 = acc[mt][nt][2], v3 = acc[mt][nt][3];
            s0 += v0 + v2; s1 += v1 + v3;
            q0 += v0 * v0 + v2 * v2; q1 += v1 * v1 + v3 * v3;
        }
#pragma unroll
        for (int off = 4; off < 32; off <<= 1) {
            s0 += __shfl_xor_sync(0xffffffffu, s0, off);
            s1 += __shfl_xor_sync(0xffffffffu, s1, off);
            q0 += __shfl_xor_sync(0xffffffffu, q0, off);
            q1 += __shfl_xor_sync(0xffffffffu, q1, off);
        }
        if (g == 0) {
            int c = wn * 32 + nt * 8 + tg * 2;
            atomicAdd(&S.s_sum[c], s0);     atomicAdd(&S.s_sq[c], q0);
            atomicAdd(&S.s_sum[c + 1], s1); atomicAdd(&S.s_sq[c + 1], q1);
        }
    }
    __syncthreads();

    if (tid < 64) {
        float mu  = S.s_sum[tid] * (1.0f / 256.0f);
        float var = S.s_sq[tid] * (1.0f / 256.0f) - mu * mu;
        S.s_mu[tid] = mu;
        S.s_rs[tid] = rsqrtf(var + LN_EPS);
    }
    __syncthreads();

    float* ob = out + (size_t)b * (C_ * HW_) + p0;
#pragma unroll
    for (int mt = 0; mt < 4; mt++) {
        int r = wm * 64 + mt * 16 + g;
#pragma unroll
        for (int nt = 0; nt < 4; nt++) {
            int c = wn * 32 + nt * 8 + tg * 2;
            float mu0 = S.s_mu[c], rs0 = S.s_rs[c];
            float mu1 = S.s_mu[c + 1], rs1 = S.s_rs[c + 1];
            float o0 = (acc[mt][nt][0] - mu0) * rs0 * gam0[mt] + bet0[mt];
            float o1 = (acc[mt][nt][1] - mu1) * rs1 * gam0[mt] + bet0[mt];
            float o2 = (acc[mt][nt][2] - mu0) * rs0 * gam1[mt] + bet1[mt];
            float o3 = (acc[mt][nt][3] - mu1) * rs1 * gam1[mt] + bet1[mt];
            *(float2*)&ob[(size_t)r * HW_ + c]       = make_float2(o0, o1);
            *(float2*)&ob[(size_t)(r + 8) * HW_ + c] = make_float2(o2, o3);
        }
    }
}

// =====================================================================
extern "C" void kernel_launch(void* const* d_in, const int* in_sizes, int n_in,
                              void* d_out, int out_size) {
    const float* x      = (const float*)d_in[0];
    const float* w_qkv  = (const float*)d_in[1];
    const float* w_out  = (const float*)d_in[2];
    const float* b_out  = (const float*)d_in[3];
    const float* gamma  = (const float*)d_in[4];
    const float* beta   = (const float*)d_in[5];
    float* out = (float*)d_out;

    cudaFuncSetAttribute(k_main, cudaFuncAttributeMaxDynamicSharedMemorySize,
                         (int)sizeof(MainSmem));
    cudaFuncSetAttribute(k_out_ln, cudaFuncAttributeMaxDynamicSharedMemorySize,
                         (int)sizeof(OutSmem));

    k_prex<<<(B_ * 128 * 1024) / 256, 256>>>(x);          // 8192 blocks
    k_prew<<<(3 * C_ * C_) / 4 / 256, 256>>>(w_qkv);      // 192 blocks

    k_main<<<1024 + 2048, 256, sizeof(MainSmem)>>>();     // q blocks, then kv

    dim3 g3(HEADS_, B_);                                  // 8 x 16
    k_weff<<<g3, 256>>>(w_out);

    k_out_ln<<<(B_ * HW_) / 64, 256, sizeof(OutSmem)>>>(b_out, gamma, beta, out);
}